// round 2
// baseline (speedup 1.0000x reference)
#include <cuda_runtime.h>
#include <math.h>

// Problem constants
#define HID   2048
#define MTOT  4096          // B*S = 2*2048
#define KVD   256           // N_KV * HEAD_DIM
#define HD    128           // head dim
#define NH    16
#define NKV   2
#define SCALING 0.08838834764831845f  // 128^-0.5

// Scratch (device globals; no runtime allocation allowed)
__device__ float g_Q[(size_t)MTOT * HID];   // scaled Q
__device__ float g_K[(size_t)MTOT * KVD];
__device__ float g_V[(size_t)MTOT * KVD];
__device__ float g_AT[(size_t)MTOT * HID];  // attention output (pre-Wo)

// ---------------------------------------------------------------------------
// Shared GEMM body: C[m0:m0+128, n0:n0+128] = (A @ B + bias) * scale
// A row-major [M x lda], B row-major [K x ldb], 256 threads, 8x8 per thread.
// ---------------------------------------------------------------------------
__device__ __forceinline__ void gemm_body(
    const float* __restrict__ A, int lda,
    const float* __restrict__ B, int ldb,
    const float* __restrict__ bias,
    float* __restrict__ C, int ldc,
    int Ksz, int m0, int n0, float scale,
    float (*As)[132], float (*Bs)[128])
{
    const int t  = threadIdx.x;
    const int tr = t >> 4;      // 0..15
    const int tc = t & 15;      // 0..15

    float acc[8][8];
#pragma unroll
    for (int i = 0; i < 8; ++i)
#pragma unroll
        for (int j = 0; j < 8; ++j) acc[i][j] = 0.f;

    for (int k0 = 0; k0 < Ksz; k0 += 16) {
        // Load A tile 128x16 transposed into As[k][m]
#pragma unroll
        for (int s = 0; s < 2; ++s) {
            int i  = t + 256 * s;          // 0..511 (float4 index)
            int r  = i >> 2;               // 0..127
            int c4 = (i & 3) << 2;         // 0,4,8,12
            float4 v = *(const float4*)(A + (size_t)(m0 + r) * lda + k0 + c4);
            As[c4 + 0][r] = v.x;
            As[c4 + 1][r] = v.y;
            As[c4 + 2][r] = v.z;
            As[c4 + 3][r] = v.w;
        }
        // Load B tile 16x128 straight into Bs[k][n]
#pragma unroll
        for (int s = 0; s < 2; ++s) {
            int i  = t + 256 * s;
            int kr = i >> 5;               // 0..15
            int nc = (i & 31) << 2;        // 0..124
            *(float4*)&Bs[kr][nc] =
                *(const float4*)(B + (size_t)(k0 + kr) * ldb + n0 + nc);
        }
        __syncthreads();

#pragma unroll
        for (int k = 0; k < 16; ++k) {
            float a[8], b[8];
            *(float4*)&a[0] = *(float4*)&As[k][8 * tr];
            *(float4*)&a[4] = *(float4*)&As[k][8 * tr + 4];
            *(float4*)&b[0] = *(float4*)&Bs[k][8 * tc];
            *(float4*)&b[4] = *(float4*)&Bs[k][8 * tc + 4];
#pragma unroll
            for (int i = 0; i < 8; ++i)
#pragma unroll
                for (int j = 0; j < 8; ++j)
                    acc[i][j] = fmaf(a[i], b[j], acc[i][j]);
        }
        __syncthreads();
    }

    // Epilogue: (acc + bias) * scale
#pragma unroll
    for (int i = 0; i < 8; ++i) {
        size_t row = (size_t)(m0 + 8 * tr + i);
#pragma unroll
        for (int j = 0; j < 8; j += 4) {
            int n = n0 + 8 * tc + j;
            float4 v;
            v.x = (acc[i][j + 0] + bias[n + 0]) * scale;
            v.y = (acc[i][j + 1] + bias[n + 1]) * scale;
            v.z = (acc[i][j + 2] + bias[n + 2]) * scale;
            v.w = (acc[i][j + 3] + bias[n + 3]) * scale;
            *(float4*)(C + row * ldc + n) = v;
        }
    }
}

// Fused QKV projection. grid = (20, 32): x<16 -> Q cols, 16..17 -> K, 18..19 -> V
__global__ __launch_bounds__(256)
void qkv_kernel(const float* __restrict__ X,
                const float* __restrict__ Wq, const float* __restrict__ bq,
                const float* __restrict__ Wk, const float* __restrict__ bk,
                const float* __restrict__ Wv, const float* __restrict__ bv)
{
    __shared__ float As[16][132];
    __shared__ float Bs[16][128];
    int gx = blockIdx.x;
    int m0 = blockIdx.y * 128;
    if (gx < 16) {
        gemm_body(X, HID, Wq, HID, bq, g_Q, HID, HID, m0, gx * 128, SCALING, As, Bs);
    } else if (gx < 18) {
        gemm_body(X, HID, Wk, KVD, bk, g_K, KVD, HID, m0, (gx - 16) * 128, 1.f, As, Bs);
    } else {
        gemm_body(X, HID, Wv, KVD, bv, g_V, KVD, HID, m0, (gx - 18) * 128, 1.f, As, Bs);
    }
}

// O projection: out = g_AT @ Wo + bo. grid = (16, 32)
__global__ __launch_bounds__(256)
void oproj_kernel(const float* __restrict__ Wo, const float* __restrict__ bo,
                  float* __restrict__ out)
{
    __shared__ float As[16][132];
    __shared__ float Bs[16][128];
    gemm_body(g_AT, HID, Wo, HID, bo, out, HID, HID,
              blockIdx.y * 128, blockIdx.x * 128, 1.f, As, Bs);
}

// ---------------------------------------------------------------------------
// Flash attention: grid = (32 q-blocks, 32 b*h), 256 threads.
// Br=Bc=64, D=128. Thread t: tr=t/16 owns rows 4tr..4tr+3,
// tc=t%16 owns S-cols 4tc..4tc+3 and O-cols 8tc..8tc+7.
// ---------------------------------------------------------------------------
#define FLASH_SMEM ((2 * 128 * 64 + 64 * 132 + 64 * 68) * 4)  // 116736 B

__global__ __launch_bounds__(256)
void flash_kernel()
{
    extern __shared__ float sm[];
    float (*Qs)[64]  = (float(*)[64])sm;                       // [128][64] (d-major)
    float (*Ks)[64]  = (float(*)[64])(sm + 128 * 64);          // [128][64]
    float (*Vs)[132] = (float(*)[132])(sm + 2 * 128 * 64);     // [64][132]
    float (*Ps)[68]  = (float(*)[68])(sm + 2 * 128 * 64 + 64 * 132); // [64][68]

    const int t  = threadIdx.x;
    const int tr = t >> 4;
    const int tc = t & 15;

    const int bh  = blockIdx.y;
    const int b   = bh >> 4;
    const int h   = bh & 15;
    const int kvh = h >> 3;          // GQA: 8 query heads per KV head
    const int q0  = blockIdx.x * 64;
    const size_t qrow0 = (size_t)(b * 2048 + q0);

    // Load Q block transposed: Qs[d][r]
#pragma unroll
    for (int s = 0; s < 8; ++s) {
        int i  = t + 256 * s;          // 0..2047 float4 index
        int r  = i >> 5;               // 0..63
        int d4 = (i & 31) << 2;        // 0..124
        float4 v = *(const float4*)(g_Q + (qrow0 + r) * HID + h * HD + d4);
        Qs[d4 + 0][r] = v.x;
        Qs[d4 + 1][r] = v.y;
        Qs[d4 + 2][r] = v.z;
        Qs[d4 + 3][r] = v.w;
    }

    float o[4][8];
#pragma unroll
    for (int i = 0; i < 4; ++i)
#pragma unroll
        for (int c = 0; c < 8; ++c) o[i][c] = 0.f;
    float m[4] = {-1e30f, -1e30f, -1e30f, -1e30f};
    float l[4] = {0.f, 0.f, 0.f, 0.f};

    for (int kb = 0; kb < 32; ++kb) {
        __syncthreads();  // prior iteration's reads of Ks/Vs/Ps complete
        const size_t krow0 = (size_t)(b * 2048 + kb * 64);
#pragma unroll
        for (int s = 0; s < 8; ++s) {
            int i  = t + 256 * s;
            int r  = i >> 5;
            int d4 = (i & 31) << 2;
            float4 kv = *(const float4*)(g_K + (krow0 + r) * KVD + kvh * HD + d4);
            Ks[d4 + 0][r] = kv.x;
            Ks[d4 + 1][r] = kv.y;
            Ks[d4 + 2][r] = kv.z;
            Ks[d4 + 3][r] = kv.w;
            float4 vv = *(const float4*)(g_V + (krow0 + r) * KVD + kvh * HD + d4);
            *(float4*)&Vs[r][d4] = vv;
        }
        __syncthreads();

        // S = Q @ K^T  (4x4 per thread)
        float s4[4][4];
#pragma unroll
        for (int i = 0; i < 4; ++i)
#pragma unroll
            for (int j = 0; j < 4; ++j) s4[i][j] = 0.f;
#pragma unroll 4
        for (int k = 0; k < 128; ++k) {
            float4 qv = *(float4*)&Qs[k][4 * tr];
            float4 kv = *(float4*)&Ks[k][4 * tc];
            float qa[4] = {qv.x, qv.y, qv.z, qv.w};
            float ka[4] = {kv.x, kv.y, kv.z, kv.w};
#pragma unroll
            for (int i = 0; i < 4; ++i)
#pragma unroll
                for (int j = 0; j < 4; ++j)
                    s4[i][j] = fmaf(qa[i], ka[j], s4[i][j]);
        }

        // Online softmax update (reduce over the 16 threads sharing a row group)
        float alpha[4];
#pragma unroll
        for (int i = 0; i < 4; ++i) {
            float mx = fmaxf(fmaxf(s4[i][0], s4[i][1]), fmaxf(s4[i][2], s4[i][3]));
            mx = fmaxf(mx, __shfl_xor_sync(0xffffffffu, mx, 8));
            mx = fmaxf(mx, __shfl_xor_sync(0xffffffffu, mx, 4));
            mx = fmaxf(mx, __shfl_xor_sync(0xffffffffu, mx, 2));
            mx = fmaxf(mx, __shfl_xor_sync(0xffffffffu, mx, 1));
            float mn = fmaxf(m[i], mx);
            alpha[i] = __expf(m[i] - mn);
            m[i] = mn;
            float ls = 0.f;
#pragma unroll
            for (int j = 0; j < 4; ++j) {
                s4[i][j] = __expf(s4[i][j] - mn);
                ls += s4[i][j];
            }
            ls += __shfl_xor_sync(0xffffffffu, ls, 8);
            ls += __shfl_xor_sync(0xffffffffu, ls, 4);
            ls += __shfl_xor_sync(0xffffffffu, ls, 2);
            ls += __shfl_xor_sync(0xffffffffu, ls, 1);
            l[i] = l[i] * alpha[i] + ls;
#pragma unroll
            for (int c = 0; c < 8; ++c) o[i][c] *= alpha[i];
            *(float4*)&Ps[4 * tr + i][4 * tc] =
                make_float4(s4[i][0], s4[i][1], s4[i][2], s4[i][3]);
        }
        __syncthreads();

        // O += P @ V
#pragma unroll 8
        for (int j = 0; j < 64; ++j) {
            float p0 = Ps[4 * tr + 0][j];
            float p1 = Ps[4 * tr + 1][j];
            float p2 = Ps[4 * tr + 2][j];
            float p3 = Ps[4 * tr + 3][j];
            float4 v0 = *(float4*)&Vs[j][8 * tc];
            float4 v1 = *(float4*)&Vs[j][8 * tc + 4];
            float va[8] = {v0.x, v0.y, v0.z, v0.w, v1.x, v1.y, v1.z, v1.w};
#pragma unroll
            for (int c = 0; c < 8; ++c) {
                o[0][c] = fmaf(p0, va[c], o[0][c]);
                o[1][c] = fmaf(p1, va[c], o[1][c]);
                o[2][c] = fmaf(p2, va[c], o[2][c]);
                o[3][c] = fmaf(p3, va[c], o[3][c]);
            }
        }
    }

    // Epilogue: normalize and write to g_AT
#pragma unroll
    for (int i = 0; i < 4; ++i) {
        float inv = 1.f / l[i];
        size_t row = qrow0 + 4 * tr + i;
        int col = h * HD + 8 * tc;
        float4 w0, w1;
        w0.x = o[i][0] * inv; w0.y = o[i][1] * inv;
        w0.z = o[i][2] * inv; w0.w = o[i][3] * inv;
        w1.x = o[i][4] * inv; w1.y = o[i][5] * inv;
        w1.z = o[i][6] * inv; w1.w = o[i][7] * inv;
        *(float4*)(g_AT + row * HID + col)     = w0;
        *(float4*)(g_AT + row * HID + col + 4) = w1;
    }
}

// ---------------------------------------------------------------------------
extern "C" void kernel_launch(void* const* d_in, const int* in_sizes, int n_in,
                              void* d_out, int out_size)
{
    (void)in_sizes; (void)n_in; (void)out_size;
    const float* X  = (const float*)d_in[0];
    const float* Wq = (const float*)d_in[1];
    const float* bq = (const float*)d_in[2];
    const float* Wk = (const float*)d_in[3];
    const float* bk = (const float*)d_in[4];
    const float* Wv = (const float*)d_in[5];
    const float* bv = (const float*)d_in[6];
    const float* Wo = (const float*)d_in[7];
    const float* bo = (const float*)d_in[8];
    float* out = (float*)d_out;

    (void)cudaFuncSetAttribute(flash_kernel,
                               cudaFuncAttributeMaxDynamicSharedMemorySize,
                               FLASH_SMEM);

    qkv_kernel<<<dim3(20, 32), 256>>>(X, Wq, bq, Wk, bk, Wv, bv);
    flash_kernel<<<dim3(32, 32), 256, FLASH_SMEM>>>();
    oproj_kernel<<<dim3(16, 32), 256>>>(Wo, bo, out);
}

// round 4
// speedup vs baseline: 1.2417x; 1.2417x over previous
#include <cuda_runtime.h>
#include <cuda_bf16.h>
#include <math.h>
#include <stdint.h>

// Problem constants
#define HID   2048
#define MTOT  4096          // B*S = 2*2048
#define KVD   256           // N_KV * HEAD_DIM
#define HD    128
#define SCALING 0.08838834764831845f  // 128^-0.5

// GEMM smem geometry
#define LDT    40                       // padded row length (elements)
#define TILEB  (128 * LDT * 2)          // one 128x32 bf16 tile = 10240 B
#define STAGE  (4 * TILEB)              // Ahi/Alo/Bhi/Blo = 40960 B
#define GSMEM  (2 * STAGE)              // double buffered = 81920 B

// ---------------------------------------------------------------------------
// Scratch (device globals; no runtime allocation allowed)
// ---------------------------------------------------------------------------
__device__ float g_Q[(size_t)MTOT * HID];
__device__ float g_K[(size_t)MTOT * KVD];
__device__ float g_V[(size_t)MTOT * KVD];
__device__ float g_AT[(size_t)MTOT * HID];

__device__ __nv_bfloat16 g_Xhi[(size_t)MTOT * HID],  g_Xlo[(size_t)MTOT * HID];
__device__ __nv_bfloat16 g_AThi[(size_t)MTOT * HID], g_ATlo[(size_t)MTOT * HID];
__device__ __nv_bfloat16 g_WqThi[(size_t)HID * HID], g_WqTlo[(size_t)HID * HID];
__device__ __nv_bfloat16 g_WkThi[(size_t)KVD * HID], g_WkTlo[(size_t)KVD * HID];
__device__ __nv_bfloat16 g_WvThi[(size_t)KVD * HID], g_WvTlo[(size_t)KVD * HID];
__device__ __nv_bfloat16 g_WoThi[(size_t)HID * HID], g_WoTlo[(size_t)HID * HID];

// ---------------------------------------------------------------------------
// Helpers: smem address, cp.async, lds, mma.sync (sm_80+ compatible)
// ---------------------------------------------------------------------------
__device__ __forceinline__ uint32_t smem_u32(const void* p) {
    uint32_t a;
    asm("{ .reg .u64 t; cvta.to.shared.u64 t, %1; cvt.u32.u64 %0, t; }"
        : "=r"(a) : "l"(p));
    return a;
}
__device__ __forceinline__ void cp16(uint32_t sa, const void* ga) {
    asm volatile("cp.async.cg.shared.global [%0], [%1], 16;"
                 :: "r"(sa), "l"(ga) : "memory");
}
__device__ __forceinline__ uint32_t lds32(uint32_t a) {
    uint32_t v;
    asm volatile("ld.shared.b32 %0, [%1];" : "=r"(v) : "r"(a));
    return v;
}
__device__ __forceinline__ void mma16816(float* c, const uint32_t* a,
                                         const uint32_t* b) {
    asm volatile(
        "mma.sync.aligned.m16n8k16.row.col.f32.bf16.bf16.f32 "
        "{%0,%1,%2,%3}, {%4,%5,%6,%7}, {%8,%9}, {%0,%1,%2,%3};"
        : "+f"(c[0]), "+f"(c[1]), "+f"(c[2]), "+f"(c[3])
        : "r"(a[0]), "r"(a[1]), "r"(a[2]), "r"(a[3]), "r"(b[0]), "r"(b[1]));
}

// ---------------------------------------------------------------------------
// fp32 -> (hi, lo) bf16 split conversions
// ---------------------------------------------------------------------------
__device__ __forceinline__ void split2(float f, __nv_bfloat16& h, __nv_bfloat16& l) {
    h = __float2bfloat16(f);
    l = __float2bfloat16(f - __bfloat162float(h));
}

__global__ __launch_bounds__(256)
void convert_rows(const float* __restrict__ src,
                  __nv_bfloat16* __restrict__ hi, __nv_bfloat16* __restrict__ lo)
{
    size_t i = ((size_t)blockIdx.x * 256 + threadIdx.x) * 4;
    float4 v = *(const float4*)(src + i);
    __nv_bfloat16 h0, h1, h2, h3, l0, l1, l2, l3;
    split2(v.x, h0, l0); split2(v.y, h1, l1);
    split2(v.z, h2, l2); split2(v.w, h3, l3);
    *(__nv_bfloat162*)(hi + i)     = __halves2bfloat162(h0, h1);
    *(__nv_bfloat162*)(hi + i + 2) = __halves2bfloat162(h2, h3);
    *(__nv_bfloat162*)(lo + i)     = __halves2bfloat162(l0, l1);
    *(__nv_bfloat162*)(lo + i + 2) = __halves2bfloat162(l2, l3);
}

// W [K x N] f32 -> WT [N x K] bf16 hi/lo. grid = (N/32, K/32), block = (32, 8)
__global__ __launch_bounds__(256)
void convert_T(const float* __restrict__ W,
               __nv_bfloat16* __restrict__ hiT, __nv_bfloat16* __restrict__ loT,
               int N, int K)
{
    __shared__ float tile[32][33];
    int n0 = blockIdx.x * 32, k0 = blockIdx.y * 32;
    int tx = threadIdx.x, ty = threadIdx.y;
#pragma unroll
    for (int j = 0; j < 4; ++j)
        tile[ty + 8 * j][tx] = W[(size_t)(k0 + ty + 8 * j) * N + n0 + tx];
    __syncthreads();
#pragma unroll
    for (int j = 0; j < 4; ++j) {
        int nn = n0 + ty + 8 * j;
        float f = tile[tx][ty + 8 * j];
        __nv_bfloat16 h, l;
        split2(f, h, l);
        hiT[(size_t)nn * K + k0 + tx] = h;
        loT[(size_t)nn * K + k0 + tx] = l;
    }
}

// ---------------------------------------------------------------------------
// Split-bf16 mma.sync GEMM: C[128x128] tile of A[Mx2048] @ B^T (+bias)*scale.
// A,B as bf16 hi/lo pairs; B stored [N x 2048] row-major. 256 threads,
// 8 warps (2 m x 4 n), warp tile 64x32, K staged 32 wide, cp.async dbuf.
// ---------------------------------------------------------------------------
__device__ void gemm_mma_body(
    const __nv_bfloat16* __restrict__ Ahi, const __nv_bfloat16* __restrict__ Alo,
    const __nv_bfloat16* __restrict__ Bhi, const __nv_bfloat16* __restrict__ Blo,
    const float* __restrict__ bias, float* __restrict__ C, int ldc,
    int m0, int n0, float scale, char* smb)
{
    const int t    = threadIdx.x;
    const int lane = t & 31, wid = t >> 5;
    const int wm   = wid & 1;        // 0..1 (64 rows)
    const int wn   = wid >> 1;       // 0..3 (32 cols)
    const int g    = lane >> 2;      // 0..7
    const int tg   = lane & 3;       // 0..3
    const uint32_t sb = smem_u32(smb);

    float acc[4][4][4];
#pragma unroll
    for (int im = 0; im < 4; ++im)
#pragma unroll
        for (int in = 0; in < 4; ++in)
#pragma unroll
            for (int r = 0; r < 4; ++r) acc[im][in][r] = 0.f;

    auto prefetch = [&](int s) {
        const int buf = s & 1;
        const int k0  = s * 32;
        const uint32_t base = sb + buf * STAGE;
#pragma unroll
        for (int i = 0; i < 2; ++i) {
            int idx = t + 256 * i;
            int r = idx >> 2, c = idx & 3;
            uint32_t so = base + (uint32_t)(r * LDT + c * 8) * 2;
            size_t ga = (size_t)(m0 + r) * HID + k0 + c * 8;
            size_t gb = (size_t)(n0 + r) * HID + k0 + c * 8;
            cp16(so,             Ahi + ga);
            cp16(so + TILEB,     Alo + ga);
            cp16(so + 2 * TILEB, Bhi + gb);
            cp16(so + 3 * TILEB, Blo + gb);
        }
        asm volatile("cp.async.commit_group;" ::: "memory");
    };

    prefetch(0);
    for (int s = 0; s < 64; ++s) {
        const int buf = s & 1;
        if (s < 63) {
            prefetch(s + 1);
            asm volatile("cp.async.wait_group 1;" ::: "memory");
        } else {
            asm volatile("cp.async.wait_group 0;" ::: "memory");
        }
        __syncthreads();

        const uint32_t base = sb + buf * STAGE;
#pragma unroll
        for (int kk = 0; kk < 32; kk += 16) {
            uint32_t ah[4][4], al[4][4], bh[4][2], bl[4][2];
#pragma unroll
            for (int im = 0; im < 4; ++im) {
                uint32_t ao = base +
                    (uint32_t)((wm * 64 + im * 16 + g) * LDT + kk + 2 * tg) * 2;
                ah[im][0] = lds32(ao);
                ah[im][1] = lds32(ao + 8 * LDT * 2);
                ah[im][2] = lds32(ao + 16);
                ah[im][3] = lds32(ao + 8 * LDT * 2 + 16);
                uint32_t ao2 = ao + TILEB;
                al[im][0] = lds32(ao2);
                al[im][1] = lds32(ao2 + 8 * LDT * 2);
                al[im][2] = lds32(ao2 + 16);
                al[im][3] = lds32(ao2 + 8 * LDT * 2 + 16);
            }
#pragma unroll
            for (int in = 0; in < 4; ++in) {
                uint32_t bo = base + 2 * TILEB +
                    (uint32_t)((wn * 32 + in * 8 + g) * LDT + kk + 2 * tg) * 2;
                bh[in][0] = lds32(bo);
                bh[in][1] = lds32(bo + 16);
                uint32_t bo2 = bo + TILEB;
                bl[in][0] = lds32(bo2);
                bl[in][1] = lds32(bo2 + 16);
            }
#pragma unroll
            for (int im = 0; im < 4; ++im)
#pragma unroll
                for (int in = 0; in < 4; ++in) {
                    mma16816(acc[im][in], ah[im], bh[in]);
                    mma16816(acc[im][in], ah[im], bl[in]);
                    mma16816(acc[im][in], al[im], bh[in]);
                }
        }
        __syncthreads();
    }

    // Epilogue: + bias, * scale
#pragma unroll
    for (int im = 0; im < 4; ++im) {
#pragma unroll
        for (int in = 0; in < 4; ++in) {
            int row = m0 + wm * 64 + im * 16 + g;
            int col = n0 + wn * 32 + in * 8 + 2 * tg;
            float2 b2 = *(const float2*)(bias + col);
            float2 v0, v1;
            v0.x = (acc[im][in][0] + b2.x) * scale;
            v0.y = (acc[im][in][1] + b2.y) * scale;
            v1.x = (acc[im][in][2] + b2.x) * scale;
            v1.y = (acc[im][in][3] + b2.y) * scale;
            *(float2*)(C + (size_t)row * ldc + col)       = v0;
            *(float2*)(C + (size_t)(row + 8) * ldc + col) = v1;
        }
    }
}

// Fused QKV projection. grid = (20, 32), block = 256.
__global__ __launch_bounds__(256, 1)
void qkv_mma(const float* __restrict__ bq, const float* __restrict__ bk,
             const float* __restrict__ bv)
{
    extern __shared__ char smb[];
    int gx = blockIdx.x, m0 = blockIdx.y * 128;
    if (gx < 16) {
        gemm_mma_body(g_Xhi, g_Xlo, g_WqThi, g_WqTlo, bq, g_Q, HID,
                      m0, gx * 128, SCALING, smb);
    } else if (gx < 18) {
        gemm_mma_body(g_Xhi, g_Xlo, g_WkThi, g_WkTlo, bk, g_K, KVD,
                      m0, (gx - 16) * 128, 1.f, smb);
    } else {
        gemm_mma_body(g_Xhi, g_Xlo, g_WvThi, g_WvTlo, bv, g_V, KVD,
                      m0, (gx - 18) * 128, 1.f, smb);
    }
}

// O projection. grid = (16, 32), block = 256.
__global__ __launch_bounds__(256, 1)
void oproj_mma(const float* __restrict__ bo, float* __restrict__ out)
{
    extern __shared__ char smb[];
    gemm_mma_body(g_AThi, g_ATlo, g_WoThi, g_WoTlo, bo, out, HID,
                  blockIdx.y * 128, blockIdx.x * 128, 1.f, smb);
}

// ---------------------------------------------------------------------------
// Flash attention (fp32 SIMT, proven): grid = (32, 32), 256 threads.
// ---------------------------------------------------------------------------
#define FLASH_SMEM ((2 * 128 * 64 + 64 * 132 + 64 * 68) * 4)  // 116736 B

__global__ __launch_bounds__(256)
void flash_kernel()
{
    extern __shared__ float sm[];
    float (*Qs)[64]  = (float(*)[64])sm;
    float (*Ks)[64]  = (float(*)[64])(sm + 128 * 64);
    float (*Vs)[132] = (float(*)[132])(sm + 2 * 128 * 64);
    float (*Ps)[68]  = (float(*)[68])(sm + 2 * 128 * 64 + 64 * 132);

    const int t  = threadIdx.x;
    const int tr = t >> 4;
    const int tc = t & 15;

    const int bh  = blockIdx.y;
    const int b   = bh >> 4;
    const int h   = bh & 15;
    const int kvh = h >> 3;
    const int q0  = blockIdx.x * 64;
    const size_t qrow0 = (size_t)(b * 2048 + q0);

#pragma unroll
    for (int s = 0; s < 8; ++s) {
        int i  = t + 256 * s;
        int r  = i >> 5;
        int d4 = (i & 31) << 2;
        float4 v = *(const float4*)(g_Q + (qrow0 + r) * HID + h * HD + d4);
        Qs[d4 + 0][r] = v.x;
        Qs[d4 + 1][r] = v.y;
        Qs[d4 + 2][r] = v.z;
        Qs[d4 + 3][r] = v.w;
    }

    float o[4][8];
#pragma unroll
    for (int i = 0; i < 4; ++i)
#pragma unroll
        for (int c = 0; c < 8; ++c) o[i][c] = 0.f;
    float m[4] = {-1e30f, -1e30f, -1e30f, -1e30f};
    float l[4] = {0.f, 0.f, 0.f, 0.f};

    for (int kb = 0; kb < 32; ++kb) {
        __syncthreads();
        const size_t krow0 = (size_t)(b * 2048 + kb * 64);
#pragma unroll
        for (int s = 0; s < 8; ++s) {
            int i  = t + 256 * s;
            int r  = i >> 5;
            int d4 = (i & 31) << 2;
            float4 kv = *(const float4*)(g_K + (krow0 + r) * KVD + kvh * HD + d4);
            Ks[d4 + 0][r] = kv.x;
            Ks[d4 + 1][r] = kv.y;
            Ks[d4 + 2][r] = kv.z;
            Ks[d4 + 3][r] = kv.w;
            float4 vv = *(const float4*)(g_V + (krow0 + r) * KVD + kvh * HD + d4);
            *(float4*)&Vs[r][d4] = vv;
        }
        __syncthreads();

        float s4[4][4];
#pragma unroll
        for (int i = 0; i < 4; ++i)
#pragma unroll
            for (int j = 0; j < 4; ++j) s4[i][j] = 0.f;
#pragma unroll 4
        for (int k = 0; k < 128; ++k) {
            float4 qv = *(float4*)&Qs[k][4 * tr];
            float4 kv = *(float4*)&Ks[k][4 * tc];
            float qa[4] = {qv.x, qv.y, qv.z, qv.w};
            float ka[4] = {kv.x, kv.y, kv.z, kv.w};
#pragma unroll
            for (int i = 0; i < 4; ++i)
#pragma unroll
                for (int j = 0; j < 4; ++j)
                    s4[i][j] = fmaf(qa[i], ka[j], s4[i][j]);
        }

        float alpha[4];
#pragma unroll
        for (int i = 0; i < 4; ++i) {
            float mx = fmaxf(fmaxf(s4[i][0], s4[i][1]), fmaxf(s4[i][2], s4[i][3]));
            mx = fmaxf(mx, __shfl_xor_sync(0xffffffffu, mx, 8));
            mx = fmaxf(mx, __shfl_xor_sync(0xffffffffu, mx, 4));
            mx = fmaxf(mx, __shfl_xor_sync(0xffffffffu, mx, 2));
            mx = fmaxf(mx, __shfl_xor_sync(0xffffffffu, mx, 1));
            float mn = fmaxf(m[i], mx);
            alpha[i] = __expf(m[i] - mn);
            m[i] = mn;
            float ls = 0.f;
#pragma unroll
            for (int j = 0; j < 4; ++j) {
                s4[i][j] = __expf(s4[i][j] - mn);
                ls += s4[i][j];
            }
            ls += __shfl_xor_sync(0xffffffffu, ls, 8);
            ls += __shfl_xor_sync(0xffffffffu, ls, 4);
            ls += __shfl_xor_sync(0xffffffffu, ls, 2);
            ls += __shfl_xor_sync(0xffffffffu, ls, 1);
            l[i] = l[i] * alpha[i] + ls;
#pragma unroll
            for (int c = 0; c < 8; ++c) o[i][c] *= alpha[i];
            *(float4*)&Ps[4 * tr + i][4 * tc] =
                make_float4(s4[i][0], s4[i][1], s4[i][2], s4[i][3]);
        }
        __syncthreads();

#pragma unroll 8
        for (int j = 0; j < 64; ++j) {
            float p0 = Ps[4 * tr + 0][j];
            float p1 = Ps[4 * tr + 1][j];
            float p2 = Ps[4 * tr + 2][j];
            float p3 = Ps[4 * tr + 3][j];
            float4 v0 = *(float4*)&Vs[j][8 * tc];
            float4 v1 = *(float4*)&Vs[j][8 * tc + 4];
            float va[8] = {v0.x, v0.y, v0.z, v0.w, v1.x, v1.y, v1.z, v1.w};
#pragma unroll
            for (int c = 0; c < 8; ++c) {
                o[0][c] = fmaf(p0, va[c], o[0][c]);
                o[1][c] = fmaf(p1, va[c], o[1][c]);
                o[2][c] = fmaf(p2, va[c], o[2][c]);
                o[3][c] = fmaf(p3, va[c], o[3][c]);
            }
        }
    }

#pragma unroll
    for (int i = 0; i < 4; ++i) {
        float inv = 1.f / l[i];
        size_t row = qrow0 + 4 * tr + i;
        int col = h * HD + 8 * tc;
        float4 w0, w1;
        w0.x = o[i][0] * inv; w0.y = o[i][1] * inv;
        w0.z = o[i][2] * inv; w0.w = o[i][3] * inv;
        w1.x = o[i][4] * inv; w1.y = o[i][5] * inv;
        w1.z = o[i][6] * inv; w1.w = o[i][7] * inv;
        *(float4*)(g_AT + row * HID + col)     = w0;
        *(float4*)(g_AT + row * HID + col + 4) = w1;
    }
}

// ---------------------------------------------------------------------------
extern "C" void kernel_launch(void* const* d_in, const int* in_sizes, int n_in,
                              void* d_out, int out_size)
{
    (void)in_sizes; (void)n_in; (void)out_size;
    const float* X  = (const float*)d_in[0];
    const float* Wq = (const float*)d_in[1];
    const float* bq = (const float*)d_in[2];
    const float* Wk = (const float*)d_in[3];
    const float* bk = (const float*)d_in[4];
    const float* Wv = (const float*)d_in[5];
    const float* bv = (const float*)d_in[6];
    const float* Wo = (const float*)d_in[7];
    const float* bo = (const float*)d_in[8];
    float* out = (float*)d_out;

    (void)cudaFuncSetAttribute(flash_kernel,
        cudaFuncAttributeMaxDynamicSharedMemorySize, FLASH_SMEM);
    (void)cudaFuncSetAttribute(qkv_mma,
        cudaFuncAttributeMaxDynamicSharedMemorySize, GSMEM);
    (void)cudaFuncSetAttribute(oproj_mma,
        cudaFuncAttributeMaxDynamicSharedMemorySize, GSMEM);

    __nv_bfloat16 *xhi, *xlo, *athi, *atlo;
    __nv_bfloat16 *wqh, *wql, *wkh, *wkl, *wvh, *wvl, *woh, *wol;
    float* at_f;
    cudaGetSymbolAddress((void**)&xhi,  g_Xhi);
    cudaGetSymbolAddress((void**)&xlo,  g_Xlo);
    cudaGetSymbolAddress((void**)&athi, g_AThi);
    cudaGetSymbolAddress((void**)&atlo, g_ATlo);
    cudaGetSymbolAddress((void**)&wqh,  g_WqThi);
    cudaGetSymbolAddress((void**)&wql,  g_WqTlo);
    cudaGetSymbolAddress((void**)&wkh,  g_WkThi);
    cudaGetSymbolAddress((void**)&wkl,  g_WkTlo);
    cudaGetSymbolAddress((void**)&wvh,  g_WvThi);
    cudaGetSymbolAddress((void**)&wvl,  g_WvTlo);
    cudaGetSymbolAddress((void**)&woh,  g_WoThi);
    cudaGetSymbolAddress((void**)&wol,  g_WoTlo);
    cudaGetSymbolAddress((void**)&at_f, g_AT);

    // 1) split-convert inputs
    convert_rows<<<(MTOT * HID) / 1024, 256>>>(X, xhi, xlo);
    convert_T<<<dim3(HID / 32, HID / 32), dim3(32, 8)>>>(Wq, wqh, wql, HID, HID);
    convert_T<<<dim3(KVD / 32, HID / 32), dim3(32, 8)>>>(Wk, wkh, wkl, KVD, HID);
    convert_T<<<dim3(KVD / 32, HID / 32), dim3(32, 8)>>>(Wv, wvh, wvl, KVD, HID);
    convert_T<<<dim3(HID / 32, HID / 32), dim3(32, 8)>>>(Wo, woh, wol, HID, HID);

    // 2) QKV projection (mma.sync split-bf16 tensor cores)
    qkv_mma<<<dim3(20, 32), 256, GSMEM>>>(bq, bk, bv);

    // 3) attention (fp32 SIMT)
    flash_kernel<<<dim3(32, 32), 256, FLASH_SMEM>>>();

    // 4) O projection
    convert_rows<<<(MTOT * HID) / 1024, 256>>>(at_f, athi, atlo);
    oproj_mma<<<dim3(16, 32), 256, GSMEM>>>(bo, out);
}

// round 5
// speedup vs baseline: 3.0341x; 2.4435x over previous
#include <cuda_runtime.h>
#include <cuda_bf16.h>
#include <cuda_fp16.h>
#include <math.h>
#include <stdint.h>

// Problem constants
#define HID   2048
#define MTOT  4096          // B*S = 2*2048
#define KVD   256           // N_KV * HEAD_DIM
#define HD    128
#define SCALING 0.08838834764831845f  // 128^-0.5

// GEMM smem geometry
#define LDT    40                       // padded row length (elements)
#define TILEB  (128 * LDT * 2)          // one 128x32 bf16 tile = 10240 B
#define STAGE  (4 * TILEB)              // Ahi/Alo/Bhi/Blo = 40960 B
#define GSMEM  (2 * STAGE)              // double buffered = 81920 B

// ---------------------------------------------------------------------------
// Scratch (device globals; no runtime allocation allowed)
// ---------------------------------------------------------------------------
__device__ __half g_Qh[(size_t)MTOT * HID];   // scaled Q (fp16)
__device__ __half g_Kh[(size_t)MTOT * KVD];
__device__ __half g_Vh[(size_t)MTOT * KVD];
__device__ float  g_AT[(size_t)MTOT * HID];   // attention output (fp32)

__device__ __nv_bfloat16 g_Xhi[(size_t)MTOT * HID],  g_Xlo[(size_t)MTOT * HID];
__device__ __nv_bfloat16 g_AThi[(size_t)MTOT * HID], g_ATlo[(size_t)MTOT * HID];
__device__ __nv_bfloat16 g_WqThi[(size_t)HID * HID], g_WqTlo[(size_t)HID * HID];
__device__ __nv_bfloat16 g_WkThi[(size_t)KVD * HID], g_WkTlo[(size_t)KVD * HID];
__device__ __nv_bfloat16 g_WvThi[(size_t)KVD * HID], g_WvTlo[(size_t)KVD * HID];
__device__ __nv_bfloat16 g_WoThi[(size_t)HID * HID], g_WoTlo[(size_t)HID * HID];

// ---------------------------------------------------------------------------
// Helpers: smem address, cp.async, lds, mma.sync (sm_80+ compatible)
// ---------------------------------------------------------------------------
__device__ __forceinline__ uint32_t smem_u32(const void* p) {
    uint32_t a;
    asm("{ .reg .u64 t; cvta.to.shared.u64 t, %1; cvt.u32.u64 %0, t; }"
        : "=r"(a) : "l"(p));
    return a;
}
__device__ __forceinline__ void cp16(uint32_t sa, const void* ga) {
    asm volatile("cp.async.cg.shared.global [%0], [%1], 16;"
                 :: "r"(sa), "l"(ga) : "memory");
}
__device__ __forceinline__ uint32_t lds32(uint32_t a) {
    uint32_t v;
    asm volatile("ld.shared.b32 %0, [%1];" : "=r"(v) : "r"(a));
    return v;
}
// bf16 mma (GEMMs)
__device__ __forceinline__ void mma_bf16(float* c, const uint32_t* a,
                                         const uint32_t* b) {
    asm volatile(
        "mma.sync.aligned.m16n8k16.row.col.f32.bf16.bf16.f32 "
        "{%0,%1,%2,%3}, {%4,%5,%6,%7}, {%8,%9}, {%0,%1,%2,%3};"
        : "+f"(c[0]), "+f"(c[1]), "+f"(c[2]), "+f"(c[3])
        : "r"(a[0]), "r"(a[1]), "r"(a[2]), "r"(a[3]), "r"(b[0]), "r"(b[1]));
}
// fp16 mma (attention)
__device__ __forceinline__ void mma_fp16(float* c, const uint32_t* a,
                                         const uint32_t* b) {
    asm volatile(
        "mma.sync.aligned.m16n8k16.row.col.f32.f16.f16.f32 "
        "{%0,%1,%2,%3}, {%4,%5,%6,%7}, {%8,%9}, {%0,%1,%2,%3};"
        : "+f"(c[0]), "+f"(c[1]), "+f"(c[2]), "+f"(c[3])
        : "r"(a[0]), "r"(a[1]), "r"(a[2]), "r"(a[3]), "r"(b[0]), "r"(b[1]));
}

// ---------------------------------------------------------------------------
// fp32 -> (hi, lo) bf16 split conversions
// ---------------------------------------------------------------------------
__device__ __forceinline__ void split2(float f, __nv_bfloat16& h, __nv_bfloat16& l) {
    h = __float2bfloat16(f);
    l = __float2bfloat16(f - __bfloat162float(h));
}

__global__ __launch_bounds__(256)
void convert_rows(const float* __restrict__ src,
                  __nv_bfloat16* __restrict__ hi, __nv_bfloat16* __restrict__ lo)
{
    size_t i = ((size_t)blockIdx.x * 256 + threadIdx.x) * 4;
    float4 v = *(const float4*)(src + i);
    __nv_bfloat16 h0, h1, h2, h3, l0, l1, l2, l3;
    split2(v.x, h0, l0); split2(v.y, h1, l1);
    split2(v.z, h2, l2); split2(v.w, h3, l3);
    *(__nv_bfloat162*)(hi + i)     = __halves2bfloat162(h0, h1);
    *(__nv_bfloat162*)(hi + i + 2) = __halves2bfloat162(h2, h3);
    *(__nv_bfloat162*)(lo + i)     = __halves2bfloat162(l0, l1);
    *(__nv_bfloat162*)(lo + i + 2) = __halves2bfloat162(l2, l3);
}

// W [K x N] f32 -> WT [N x K] bf16 hi/lo. grid = (N/32, K/32), block = (32, 8)
__global__ __launch_bounds__(256)
void convert_T(const float* __restrict__ W,
               __nv_bfloat16* __restrict__ hiT, __nv_bfloat16* __restrict__ loT,
               int N, int K)
{
    __shared__ float tile[32][33];
    int n0 = blockIdx.x * 32, k0 = blockIdx.y * 32;
    int tx = threadIdx.x, ty = threadIdx.y;
#pragma unroll
    for (int j = 0; j < 4; ++j)
        tile[ty + 8 * j][tx] = W[(size_t)(k0 + ty + 8 * j) * N + n0 + tx];
    __syncthreads();
#pragma unroll
    for (int j = 0; j < 4; ++j) {
        int nn = n0 + ty + 8 * j;
        float f = tile[tx][ty + 8 * j];
        __nv_bfloat16 h, l;
        split2(f, h, l);
        hiT[(size_t)nn * K + k0 + tx] = h;
        loT[(size_t)nn * K + k0 + tx] = l;
    }
}

// ---------------------------------------------------------------------------
// Split-bf16 mma.sync GEMM: C[128x128] tile of A[Mx2048] @ B^T (+bias)*scale.
// Output fp16 (Ch) or fp32 (Cf). 256 threads, 8 warps (2m x 4n), warp 64x32.
// ---------------------------------------------------------------------------
__device__ void gemm_mma_body(
    const __nv_bfloat16* __restrict__ Ahi, const __nv_bfloat16* __restrict__ Alo,
    const __nv_bfloat16* __restrict__ Bhi, const __nv_bfloat16* __restrict__ Blo,
    const float* __restrict__ bias, float* __restrict__ Cf, __half* __restrict__ Ch,
    int ldc, int m0, int n0, float scale, char* smb)
{
    const int t    = threadIdx.x;
    const int lane = t & 31, wid = t >> 5;
    const int wm   = wid & 1;
    const int wn   = wid >> 1;
    const int g    = lane >> 2;
    const int tg   = lane & 3;
    const uint32_t sb = smem_u32(smb);

    float acc[4][4][4];
#pragma unroll
    for (int im = 0; im < 4; ++im)
#pragma unroll
        for (int in = 0; in < 4; ++in)
#pragma unroll
            for (int r = 0; r < 4; ++r) acc[im][in][r] = 0.f;

    auto prefetch = [&](int s) {
        const int buf = s & 1;
        const int k0  = s * 32;
        const uint32_t base = sb + buf * STAGE;
#pragma unroll
        for (int i = 0; i < 2; ++i) {
            int idx = t + 256 * i;
            int r = idx >> 2, c = idx & 3;
            uint32_t so = base + (uint32_t)(r * LDT + c * 8) * 2;
            size_t ga = (size_t)(m0 + r) * HID + k0 + c * 8;
            size_t gb = (size_t)(n0 + r) * HID + k0 + c * 8;
            cp16(so,             Ahi + ga);
            cp16(so + TILEB,     Alo + ga);
            cp16(so + 2 * TILEB, Bhi + gb);
            cp16(so + 3 * TILEB, Blo + gb);
        }
        asm volatile("cp.async.commit_group;" ::: "memory");
    };

    prefetch(0);
    for (int s = 0; s < 64; ++s) {
        const int buf = s & 1;
        if (s < 63) {
            prefetch(s + 1);
            asm volatile("cp.async.wait_group 1;" ::: "memory");
        } else {
            asm volatile("cp.async.wait_group 0;" ::: "memory");
        }
        __syncthreads();

        const uint32_t base = sb + buf * STAGE;
#pragma unroll
        for (int kk = 0; kk < 32; kk += 16) {
            uint32_t ah[4][4], al[4][4], bh[4][2], bl[4][2];
#pragma unroll
            for (int im = 0; im < 4; ++im) {
                uint32_t ao = base +
                    (uint32_t)((wm * 64 + im * 16 + g) * LDT + kk + 2 * tg) * 2;
                ah[im][0] = lds32(ao);
                ah[im][1] = lds32(ao + 8 * LDT * 2);
                ah[im][2] = lds32(ao + 16);
                ah[im][3] = lds32(ao + 8 * LDT * 2 + 16);
                uint32_t ao2 = ao + TILEB;
                al[im][0] = lds32(ao2);
                al[im][1] = lds32(ao2 + 8 * LDT * 2);
                al[im][2] = lds32(ao2 + 16);
                al[im][3] = lds32(ao2 + 8 * LDT * 2 + 16);
            }
#pragma unroll
            for (int in = 0; in < 4; ++in) {
                uint32_t bo = base + 2 * TILEB +
                    (uint32_t)((wn * 32 + in * 8 + g) * LDT + kk + 2 * tg) * 2;
                bh[in][0] = lds32(bo);
                bh[in][1] = lds32(bo + 16);
                uint32_t bo2 = bo + TILEB;
                bl[in][0] = lds32(bo2);
                bl[in][1] = lds32(bo2 + 16);
            }
#pragma unroll
            for (int im = 0; im < 4; ++im)
#pragma unroll
                for (int in = 0; in < 4; ++in) {
                    mma_bf16(acc[im][in], ah[im], bh[in]);
                    mma_bf16(acc[im][in], ah[im], bl[in]);
                    mma_bf16(acc[im][in], al[im], bh[in]);
                }
        }
        __syncthreads();
    }

    // Epilogue: + bias, * scale
#pragma unroll
    for (int im = 0; im < 4; ++im) {
#pragma unroll
        for (int in = 0; in < 4; ++in) {
            int row = m0 + wm * 64 + im * 16 + g;
            int col = n0 + wn * 32 + in * 8 + 2 * tg;
            float2 b2 = *(const float2*)(bias + col);
            float x0 = (acc[im][in][0] + b2.x) * scale;
            float x1 = (acc[im][in][1] + b2.y) * scale;
            float x2 = (acc[im][in][2] + b2.x) * scale;
            float x3 = (acc[im][in][3] + b2.y) * scale;
            if (Ch) {
                *(__half2*)(Ch + (size_t)row * ldc + col) = __floats2half2_rn(x0, x1);
                *(__half2*)(Ch + (size_t)(row + 8) * ldc + col) = __floats2half2_rn(x2, x3);
            } else {
                *(float2*)(Cf + (size_t)row * ldc + col)       = make_float2(x0, x1);
                *(float2*)(Cf + (size_t)(row + 8) * ldc + col) = make_float2(x2, x3);
            }
        }
    }
}

// Fused QKV projection. grid = (20, 32), block = 256. Outputs fp16.
__global__ __launch_bounds__(256, 1)
void qkv_mma(const float* __restrict__ bq, const float* __restrict__ bk,
             const float* __restrict__ bv)
{
    extern __shared__ char smb[];
    int gx = blockIdx.x, m0 = blockIdx.y * 128;
    if (gx < 16) {
        gemm_mma_body(g_Xhi, g_Xlo, g_WqThi, g_WqTlo, bq, nullptr, g_Qh, HID,
                      m0, gx * 128, SCALING, smb);
    } else if (gx < 18) {
        gemm_mma_body(g_Xhi, g_Xlo, g_WkThi, g_WkTlo, bk, nullptr, g_Kh, KVD,
                      m0, (gx - 16) * 128, 1.f, smb);
    } else {
        gemm_mma_body(g_Xhi, g_Xlo, g_WvThi, g_WvTlo, bv, nullptr, g_Vh, KVD,
                      m0, (gx - 18) * 128, 1.f, smb);
    }
}

// O projection. grid = (16, 32), block = 256. Outputs fp32.
__global__ __launch_bounds__(256, 1)
void oproj_mma(const float* __restrict__ bo, float* __restrict__ out)
{
    extern __shared__ char smb[];
    gemm_mma_body(g_AThi, g_ATlo, g_WoThi, g_WoTlo, bo, out, nullptr, HID,
                  blockIdx.y * 128, blockIdx.x * 128, 1.f, smb);
}

// ---------------------------------------------------------------------------
// Flash attention with fp16 mma.sync. grid = (32 qblocks, 32 bh), 128 threads.
// Br = 64 (16 rows/warp), Bc = 64, D = 128. FA2 register pipeline:
// S frags in regs -> softmax in regs -> repack as A frags for PV mma.
// ---------------------------------------------------------------------------
#define FL_LDK 136
#define FL_LDV 72
#define FL_SMEM ((2 * 64 * FL_LDK + 128 * FL_LDV) * 2)  // 53248 B

__global__ __launch_bounds__(128, 2)
void flash_mma()
{
    extern __shared__ __half fsm[];
    __half* Qs = fsm;                    // [64][136]
    __half* Ks = fsm + 64 * FL_LDK;      // [64][136]
    __half* Vt = fsm + 2 * 64 * FL_LDK;  // [128][72] (d-major)

    const int t = threadIdx.x, lane = t & 31, warp = t >> 5;
    const int g = lane >> 2, tg = lane & 3;
    const int bh = blockIdx.y, b = bh >> 4, h = bh & 15, kvh = h >> 3;
    const int q0 = blockIdx.x * 64;
    const size_t qrow0 = (size_t)(b * 2048 + q0);
    const uint32_t sQ = smem_u32(Qs), sK = smem_u32(Ks), sV = smem_u32(Vt);

    // Stage Q tile 64x128 fp16
#pragma unroll
    for (int s = 0; s < 8; ++s) {
        int i = t + 128 * s;
        int r = i >> 4, cg = i & 15;
        *(uint4*)(Qs + r * FL_LDK + cg * 8) =
            *(const uint4*)(g_Qh + (qrow0 + r) * HID + h * HD + cg * 8);
    }
    __syncthreads();

    // Q fragments: warp covers rows [warp*16, warp*16+16), all 128 d (8 k-steps)
    uint32_t aQ[8][4];
    const int wr = warp * 16;
#pragma unroll
    for (int ks = 0; ks < 8; ++ks) {
        uint32_t ao = sQ + (uint32_t)((wr + g) * FL_LDK + ks * 16 + 2 * tg) * 2;
        aQ[ks][0] = lds32(ao);
        aQ[ks][1] = lds32(ao + 8 * FL_LDK * 2);
        aQ[ks][2] = lds32(ao + 16);
        aQ[ks][3] = lds32(ao + 8 * FL_LDK * 2 + 16);
    }

    float oacc[16][4];
#pragma unroll
    for (int j = 0; j < 16; ++j)
#pragma unroll
        for (int r = 0; r < 4; ++r) oacc[j][r] = 0.f;
    float mrow0 = -1e30f, mrow1 = -1e30f, lrow0 = 0.f, lrow1 = 0.f;

    for (int kb = 0; kb < 32; ++kb) {
        __syncthreads();
        const size_t krow0 = (size_t)(b * 2048 + kb * 64);
#pragma unroll
        for (int s = 0; s < 8; ++s) {
            int i = t + 128 * s;
            int r = i >> 4, cg = i & 15;
            *(uint4*)(Ks + r * FL_LDK + cg * 8) =
                *(const uint4*)(g_Kh + (krow0 + r) * KVD + kvh * HD + cg * 8);
            uint4 vv = *(const uint4*)(g_Vh + (krow0 + r) * KVD + kvh * HD + cg * 8);
            const __half* vh = (const __half*)&vv;
#pragma unroll
            for (int j = 0; j < 8; ++j) Vt[(cg * 8 + j) * FL_LDV + r] = vh[j];
        }
        __syncthreads();

        // S = Q @ K^T : 8 n8-tiles (64 cols)
        float sacc[8][4];
#pragma unroll
        for (int j = 0; j < 8; ++j)
#pragma unroll
            for (int r = 0; r < 4; ++r) sacc[j][r] = 0.f;
#pragma unroll
        for (int ks = 0; ks < 8; ++ks) {
            uint32_t bK[8][2];
#pragma unroll
            for (int j = 0; j < 8; ++j) {
                uint32_t bo = sK + (uint32_t)((8 * j + g) * FL_LDK + ks * 16 + 2 * tg) * 2;
                bK[j][0] = lds32(bo);
                bK[j][1] = lds32(bo + 16);
            }
#pragma unroll
            for (int j = 0; j < 8; ++j) mma_fp16(sacc[j], aQ[ks], bK[j]);
        }

        // Online softmax (rows g and g+8 of warp tile)
        float mx0 = -1e30f, mx1 = -1e30f;
#pragma unroll
        for (int j = 0; j < 8; ++j) {
            mx0 = fmaxf(mx0, fmaxf(sacc[j][0], sacc[j][1]));
            mx1 = fmaxf(mx1, fmaxf(sacc[j][2], sacc[j][3]));
        }
        mx0 = fmaxf(mx0, __shfl_xor_sync(0xffffffffu, mx0, 1));
        mx0 = fmaxf(mx0, __shfl_xor_sync(0xffffffffu, mx0, 2));
        mx1 = fmaxf(mx1, __shfl_xor_sync(0xffffffffu, mx1, 1));
        mx1 = fmaxf(mx1, __shfl_xor_sync(0xffffffffu, mx1, 2));
        float mn0 = fmaxf(mrow0, mx0), mn1 = fmaxf(mrow1, mx1);
        float al0 = __expf(mrow0 - mn0), al1 = __expf(mrow1 - mn1);
        mrow0 = mn0; mrow1 = mn1;

        uint32_t aP[4][4];
        float s0 = 0.f, s1 = 0.f;
#pragma unroll
        for (int j = 0; j < 8; ++j) {
            float p0 = __expf(sacc[j][0] - mn0);
            float p1 = __expf(sacc[j][1] - mn0);
            float p2 = __expf(sacc[j][2] - mn1);
            float p3 = __expf(sacc[j][3] - mn1);
            s0 += p0 + p1; s1 += p2 + p3;
            __half2 h01 = __floats2half2_rn(p0, p1);
            __half2 h23 = __floats2half2_rn(p2, p3);
            int ks = j >> 1, hi = (j & 1) * 2;
            aP[ks][hi]     = *(uint32_t*)&h01;
            aP[ks][hi + 1] = *(uint32_t*)&h23;
        }
        s0 += __shfl_xor_sync(0xffffffffu, s0, 1);
        s0 += __shfl_xor_sync(0xffffffffu, s0, 2);
        s1 += __shfl_xor_sync(0xffffffffu, s1, 1);
        s1 += __shfl_xor_sync(0xffffffffu, s1, 2);
        lrow0 = lrow0 * al0 + s0;
        lrow1 = lrow1 * al1 + s1;

#pragma unroll
        for (int j = 0; j < 16; ++j) {
            oacc[j][0] *= al0; oacc[j][1] *= al0;
            oacc[j][2] *= al1; oacc[j][3] *= al1;
        }

        // O += P @ V : 16 d-tiles, 4 k-steps
#pragma unroll
        for (int ks = 0; ks < 4; ++ks) {
#pragma unroll
            for (int j = 0; j < 16; ++j) {
                uint32_t bo = sV + (uint32_t)((8 * j + g) * FL_LDV + ks * 16 + 2 * tg) * 2;
                uint32_t bV[2];
                bV[0] = lds32(bo);
                bV[1] = lds32(bo + 16);
                mma_fp16(oacc[j], aP[ks], bV);
            }
        }
    }

    // Epilogue: normalize, write fp32 to g_AT
    float i0 = 1.f / lrow0, i1 = 1.f / lrow1;
    size_t row0 = qrow0 + wr + g;
#pragma unroll
    for (int j = 0; j < 16; ++j) {
        int col = h * HD + 8 * j + 2 * tg;
        *(float2*)(g_AT + row0 * HID + col) =
            make_float2(oacc[j][0] * i0, oacc[j][1] * i0);
        *(float2*)(g_AT + (row0 + 8) * HID + col) =
            make_float2(oacc[j][2] * i1, oacc[j][3] * i1);
    }
}

// ---------------------------------------------------------------------------
extern "C" void kernel_launch(void* const* d_in, const int* in_sizes, int n_in,
                              void* d_out, int out_size)
{
    (void)in_sizes; (void)n_in; (void)out_size;
    const float* X  = (const float*)d_in[0];
    const float* Wq = (const float*)d_in[1];
    const float* bq = (const float*)d_in[2];
    const float* Wk = (const float*)d_in[3];
    const float* bk = (const float*)d_in[4];
    const float* Wv = (const float*)d_in[5];
    const float* bv = (const float*)d_in[6];
    const float* Wo = (const float*)d_in[7];
    const float* bo = (const float*)d_in[8];
    float* out = (float*)d_out;

    (void)cudaFuncSetAttribute(flash_mma,
        cudaFuncAttributeMaxDynamicSharedMemorySize, FL_SMEM);
    (void)cudaFuncSetAttribute(qkv_mma,
        cudaFuncAttributeMaxDynamicSharedMemorySize, GSMEM);
    (void)cudaFuncSetAttribute(oproj_mma,
        cudaFuncAttributeMaxDynamicSharedMemorySize, GSMEM);

    __nv_bfloat16 *xhi, *xlo, *athi, *atlo;
    __nv_bfloat16 *wqh, *wql, *wkh, *wkl, *wvh, *wvl, *woh, *wol;
    float* at_f;
    cudaGetSymbolAddress((void**)&xhi,  g_Xhi);
    cudaGetSymbolAddress((void**)&xlo,  g_Xlo);
    cudaGetSymbolAddress((void**)&athi, g_AThi);
    cudaGetSymbolAddress((void**)&atlo, g_ATlo);
    cudaGetSymbolAddress((void**)&wqh,  g_WqThi);
    cudaGetSymbolAddress((void**)&wql,  g_WqTlo);
    cudaGetSymbolAddress((void**)&wkh,  g_WkThi);
    cudaGetSymbolAddress((void**)&wkl,  g_WkTlo);
    cudaGetSymbolAddress((void**)&wvh,  g_WvThi);
    cudaGetSymbolAddress((void**)&wvl,  g_WvTlo);
    cudaGetSymbolAddress((void**)&woh,  g_WoThi);
    cudaGetSymbolAddress((void**)&wol,  g_WoTlo);
    cudaGetSymbolAddress((void**)&at_f, g_AT);

    // 1) split-convert inputs
    convert_rows<<<(MTOT * HID) / 1024, 256>>>(X, xhi, xlo);
    convert_T<<<dim3(HID / 32, HID / 32), dim3(32, 8)>>>(Wq, wqh, wql, HID, HID);
    convert_T<<<dim3(KVD / 32, HID / 32), dim3(32, 8)>>>(Wk, wkh, wkl, KVD, HID);
    convert_T<<<dim3(KVD / 32, HID / 32), dim3(32, 8)>>>(Wv, wvh, wvl, KVD, HID);
    convert_T<<<dim3(HID / 32, HID / 32), dim3(32, 8)>>>(Wo, woh, wol, HID, HID);

    // 2) QKV projection (split-bf16 tensor cores, fp16 outputs)
    qkv_mma<<<dim3(20, 32), 256, GSMEM>>>(bq, bk, bv);

    // 3) attention (fp16 mma.sync flash)
    flash_mma<<<dim3(32, 32), 128, FL_SMEM>>>();

    // 4) O projection
    convert_rows<<<(MTOT * HID) / 1024, 256>>>(at_f, athi, atlo);
    oproj_mma<<<dim3(16, 32), 256, GSMEM>>>(bo, out);
}

// round 6
// speedup vs baseline: 4.4172x; 1.4558x over previous
#include <cuda_runtime.h>
#include <cuda_fp16.h>
#include <math.h>
#include <stdint.h>

// Problem constants
#define HID   2048
#define MTOT  4096          // B*S = 2*2048
#define KVD   256           // N_KV * HEAD_DIM
#define HD    128
#define SCALING 0.08838834764831845f  // 128^-0.5

// GEMM smem geometry (fp16 single precision path)
#define LDT    40                       // padded row length (elements)
#define TILEB  (128 * LDT * 2)          // one 128x32 fp16 tile = 10240 B
#define STAGE  (2 * TILEB)              // A + B = 20480 B
#define GSMEM  (2 * STAGE)              // double buffered = 40960 B

// ---------------------------------------------------------------------------
// Scratch (device globals; no runtime allocation allowed)
// ---------------------------------------------------------------------------
__device__ __half g_Qh[(size_t)MTOT * HID];   // scaled Q (fp16)
__device__ __half g_Kh[(size_t)MTOT * KVD];
__device__ __half g_Vh[(size_t)MTOT * KVD];
__device__ __half g_ATh[(size_t)MTOT * HID];  // attention output (fp16)

__device__ __half g_Xh[(size_t)MTOT * HID];   // hidden states fp16
__device__ __half g_WqTh[(size_t)HID * HID];  // W^T fp16
__device__ __half g_WkTh[(size_t)KVD * HID];
__device__ __half g_WvTh[(size_t)KVD * HID];
__device__ __half g_WoTh[(size_t)HID * HID];

// ---------------------------------------------------------------------------
// Helpers
// ---------------------------------------------------------------------------
__device__ __forceinline__ uint32_t smem_u32(const void* p) {
    uint32_t a;
    asm("{ .reg .u64 t; cvta.to.shared.u64 t, %1; cvt.u32.u64 %0, t; }"
        : "=r"(a) : "l"(p));
    return a;
}
__device__ __forceinline__ void cp16(uint32_t sa, const void* ga) {
    asm volatile("cp.async.cg.shared.global [%0], [%1], 16;"
                 :: "r"(sa), "l"(ga) : "memory");
}
__device__ __forceinline__ uint32_t lds32(uint32_t a) {
    uint32_t v;
    asm volatile("ld.shared.b32 %0, [%1];" : "=r"(v) : "r"(a));
    return v;
}
__device__ __forceinline__ void mma_fp16(float* c, const uint32_t* a,
                                         const uint32_t* b) {
    asm volatile(
        "mma.sync.aligned.m16n8k16.row.col.f32.f16.f16.f32 "
        "{%0,%1,%2,%3}, {%4,%5,%6,%7}, {%8,%9}, {%0,%1,%2,%3};"
        : "+f"(c[0]), "+f"(c[1]), "+f"(c[2]), "+f"(c[3])
        : "r"(a[0]), "r"(a[1]), "r"(a[2]), "r"(a[3]), "r"(b[0]), "r"(b[1]));
}

// ---------------------------------------------------------------------------
// Converts: fp32 -> fp16
// ---------------------------------------------------------------------------
__global__ __launch_bounds__(256)
void convert_rows_h(const float* __restrict__ src, __half* __restrict__ dst)
{
    size_t i = ((size_t)blockIdx.x * 256 + threadIdx.x) * 4;
    float4 v = *(const float4*)(src + i);
    *(__half2*)(dst + i)     = __floats2half2_rn(v.x, v.y);
    *(__half2*)(dst + i + 2) = __floats2half2_rn(v.z, v.w);
}

// W [K x N] f32 -> WT [N x K] fp16. grid = (N/32, K/32), block = (32, 8)
__global__ __launch_bounds__(256)
void convert_T_h(const float* __restrict__ W, __half* __restrict__ WT,
                 int N, int K)
{
    __shared__ float tile[32][33];
    int n0 = blockIdx.x * 32, k0 = blockIdx.y * 32;
    int tx = threadIdx.x, ty = threadIdx.y;
#pragma unroll
    for (int j = 0; j < 4; ++j)
        tile[ty + 8 * j][tx] = W[(size_t)(k0 + ty + 8 * j) * N + n0 + tx];
    __syncthreads();
#pragma unroll
    for (int j = 0; j < 4; ++j) {
        int nn = n0 + ty + 8 * j;
        WT[(size_t)nn * K + k0 + tx] = __float2half_rn(tile[tx][ty + 8 * j]);
    }
}

// ---------------------------------------------------------------------------
// fp16 mma.sync GEMM: C[128x128] tile of A[Mx2048] @ B^T (+bias)*scale.
// A fp16 [M][2048], B fp16 [N][2048] (transposed weights). 256 threads,
// 8 warps (2m x 4n), warp tile 64x32, K staged 32 wide, cp.async dbuf.
// Output fp16 (Ch) or fp32 (Cf).
// ---------------------------------------------------------------------------
__device__ void gemm_fp16_body(
    const __half* __restrict__ A, const __half* __restrict__ B,
    const float* __restrict__ bias, float* __restrict__ Cf,
    __half* __restrict__ Ch, int ldc, int m0, int n0, float scale, char* smb)
{
    const int t    = threadIdx.x;
    const int lane = t & 31, wid = t >> 5;
    const int wm   = wid & 1;        // 0..1 (64 rows)
    const int wn   = wid >> 1;       // 0..3 (32 cols)
    const int g    = lane >> 2;      // 0..7
    const int tg   = lane & 3;       // 0..3
    const uint32_t sb = smem_u32(smb);

    float acc[4][4][4];
#pragma unroll
    for (int im = 0; im < 4; ++im)
#pragma unroll
        for (int in = 0; in < 4; ++in)
#pragma unroll
            for (int r = 0; r < 4; ++r) acc[im][in][r] = 0.f;

    auto prefetch = [&](int s) {
        const int buf = s & 1;
        const int k0  = s * 32;
        const uint32_t base = sb + buf * STAGE;
#pragma unroll
        for (int i = 0; i < 2; ++i) {
            int idx = t + 256 * i;          // 0..511
            int r = idx >> 2, c = idx & 3;  // r 0..127, c 0..3 (8 halves)
            uint32_t so = base + (uint32_t)(r * LDT + c * 8) * 2;
            cp16(so,         A + (size_t)(m0 + r) * HID + k0 + c * 8);
            cp16(so + TILEB, B + (size_t)(n0 + r) * HID + k0 + c * 8);
        }
        asm volatile("cp.async.commit_group;" ::: "memory");
    };

    prefetch(0);
    for (int s = 0; s < 64; ++s) {
        const int buf = s & 1;
        if (s < 63) {
            prefetch(s + 1);
            asm volatile("cp.async.wait_group 1;" ::: "memory");
        } else {
            asm volatile("cp.async.wait_group 0;" ::: "memory");
        }
        __syncthreads();

        const uint32_t base = sb + buf * STAGE;
#pragma unroll
        for (int kk = 0; kk < 32; kk += 16) {
            uint32_t ah[4][4], bh[4][2];
#pragma unroll
            for (int im = 0; im < 4; ++im) {
                uint32_t ao = base +
                    (uint32_t)((wm * 64 + im * 16 + g) * LDT + kk + 2 * tg) * 2;
                ah[im][0] = lds32(ao);
                ah[im][1] = lds32(ao + 8 * LDT * 2);
                ah[im][2] = lds32(ao + 16);
                ah[im][3] = lds32(ao + 8 * LDT * 2 + 16);
            }
#pragma unroll
            for (int in = 0; in < 4; ++in) {
                uint32_t bo = base + TILEB +
                    (uint32_t)((wn * 32 + in * 8 + g) * LDT + kk + 2 * tg) * 2;
                bh[in][0] = lds32(bo);
                bh[in][1] = lds32(bo + 16);
            }
#pragma unroll
            for (int im = 0; im < 4; ++im)
#pragma unroll
                for (int in = 0; in < 4; ++in)
                    mma_fp16(acc[im][in], ah[im], bh[in]);
        }
        __syncthreads();
    }

    // Epilogue: + bias, * scale
#pragma unroll
    for (int im = 0; im < 4; ++im) {
#pragma unroll
        for (int in = 0; in < 4; ++in) {
            int row = m0 + wm * 64 + im * 16 + g;
            int col = n0 + wn * 32 + in * 8 + 2 * tg;
            float2 b2 = *(const float2*)(bias + col);
            float x0 = (acc[im][in][0] + b2.x) * scale;
            float x1 = (acc[im][in][1] + b2.y) * scale;
            float x2 = (acc[im][in][2] + b2.x) * scale;
            float x3 = (acc[im][in][3] + b2.y) * scale;
            if (Ch) {
                *(__half2*)(Ch + (size_t)row * ldc + col) = __floats2half2_rn(x0, x1);
                *(__half2*)(Ch + (size_t)(row + 8) * ldc + col) = __floats2half2_rn(x2, x3);
            } else {
                *(float2*)(Cf + (size_t)row * ldc + col)       = make_float2(x0, x1);
                *(float2*)(Cf + (size_t)(row + 8) * ldc + col) = make_float2(x2, x3);
            }
        }
    }
}

// Fused QKV projection. grid = (20, 32), block = 256. Outputs fp16.
__global__ __launch_bounds__(256)
void qkv_mma(const float* __restrict__ bq, const float* __restrict__ bk,
             const float* __restrict__ bv)
{
    extern __shared__ char smb[];
    int gx = blockIdx.x, m0 = blockIdx.y * 128;
    if (gx < 16) {
        gemm_fp16_body(g_Xh, g_WqTh, bq, nullptr, g_Qh, HID,
                       m0, gx * 128, SCALING, smb);
    } else if (gx < 18) {
        gemm_fp16_body(g_Xh, g_WkTh, bk, nullptr, g_Kh, KVD,
                       m0, (gx - 16) * 128, 1.f, smb);
    } else {
        gemm_fp16_body(g_Xh, g_WvTh, bv, nullptr, g_Vh, KVD,
                       m0, (gx - 18) * 128, 1.f, smb);
    }
}

// O projection. grid = (16, 32), block = 256. Outputs fp32.
__global__ __launch_bounds__(256)
void oproj_mma(const float* __restrict__ bo, float* __restrict__ out)
{
    extern __shared__ char smb[];
    gemm_fp16_body(g_ATh, g_WoTh, bo, out, nullptr, HID,
                   blockIdx.y * 128, blockIdx.x * 128, 1.f, smb);
}

// ---------------------------------------------------------------------------
// Flash attention with fp16 mma.sync. grid = (32 qblocks, 32 bh), 128 threads.
// Br = 64 (16 rows/warp), Bc = 64, D = 128. FA2 register pipeline.
// ---------------------------------------------------------------------------
#define FL_LDK 136
#define FL_LDV 72
#define FL_SMEM ((2 * 64 * FL_LDK + 128 * FL_LDV) * 2)  // 53248 B

__global__ __launch_bounds__(128, 2)
void flash_mma()
{
    extern __shared__ __half fsm[];
    __half* Qs = fsm;                    // [64][136]
    __half* Ks = fsm + 64 * FL_LDK;      // [64][136]
    __half* Vt = fsm + 2 * 64 * FL_LDK;  // [128][72] (d-major)

    const int t = threadIdx.x, lane = t & 31, warp = t >> 5;
    const int g = lane >> 2, tg = lane & 3;
    const int bh = blockIdx.y, b = bh >> 4, h = bh & 15, kvh = h >> 3;
    const int q0 = blockIdx.x * 64;
    const size_t qrow0 = (size_t)(b * 2048 + q0);
    const uint32_t sQ = smem_u32(Qs), sK = smem_u32(Ks), sV = smem_u32(Vt);

    // Stage Q tile 64x128 fp16
#pragma unroll
    for (int s = 0; s < 8; ++s) {
        int i = t + 128 * s;
        int r = i >> 4, cg = i & 15;
        *(uint4*)(Qs + r * FL_LDK + cg * 8) =
            *(const uint4*)(g_Qh + (qrow0 + r) * HID + h * HD + cg * 8);
    }
    __syncthreads();

    // Q fragments: warp covers rows [warp*16, warp*16+16), 8 k-steps
    uint32_t aQ[8][4];
    const int wr = warp * 16;
#pragma unroll
    for (int ks = 0; ks < 8; ++ks) {
        uint32_t ao = sQ + (uint32_t)((wr + g) * FL_LDK + ks * 16 + 2 * tg) * 2;
        aQ[ks][0] = lds32(ao);
        aQ[ks][1] = lds32(ao + 8 * FL_LDK * 2);
        aQ[ks][2] = lds32(ao + 16);
        aQ[ks][3] = lds32(ao + 8 * FL_LDK * 2 + 16);
    }

    float oacc[16][4];
#pragma unroll
    for (int j = 0; j < 16; ++j)
#pragma unroll
        for (int r = 0; r < 4; ++r) oacc[j][r] = 0.f;
    float mrow0 = -1e30f, mrow1 = -1e30f, lrow0 = 0.f, lrow1 = 0.f;

    for (int kb = 0; kb < 32; ++kb) {
        __syncthreads();
        const size_t krow0 = (size_t)(b * 2048 + kb * 64);
#pragma unroll
        for (int s = 0; s < 8; ++s) {
            int i = t + 128 * s;
            int r = i >> 4, cg = i & 15;
            *(uint4*)(Ks + r * FL_LDK + cg * 8) =
                *(const uint4*)(g_Kh + (krow0 + r) * KVD + kvh * HD + cg * 8);
            uint4 vv = *(const uint4*)(g_Vh + (krow0 + r) * KVD + kvh * HD + cg * 8);
            const __half* vh = (const __half*)&vv;
#pragma unroll
            for (int j = 0; j < 8; ++j) Vt[(cg * 8 + j) * FL_LDV + r] = vh[j];
        }
        __syncthreads();

        // S = Q @ K^T : 8 n8-tiles (64 cols)
        float sacc[8][4];
#pragma unroll
        for (int j = 0; j < 8; ++j)
#pragma unroll
            for (int r = 0; r < 4; ++r) sacc[j][r] = 0.f;
#pragma unroll
        for (int ks = 0; ks < 8; ++ks) {
            uint32_t bK[8][2];
#pragma unroll
            for (int j = 0; j < 8; ++j) {
                uint32_t bo = sK + (uint32_t)((8 * j + g) * FL_LDK + ks * 16 + 2 * tg) * 2;
                bK[j][0] = lds32(bo);
                bK[j][1] = lds32(bo + 16);
            }
#pragma unroll
            for (int j = 0; j < 8; ++j) mma_fp16(sacc[j], aQ[ks], bK[j]);
        }

        // Online softmax (rows g and g+8 of warp tile)
        float mx0 = -1e30f, mx1 = -1e30f;
#pragma unroll
        for (int j = 0; j < 8; ++j) {
            mx0 = fmaxf(mx0, fmaxf(sacc[j][0], sacc[j][1]));
            mx1 = fmaxf(mx1, fmaxf(sacc[j][2], sacc[j][3]));
        }
        mx0 = fmaxf(mx0, __shfl_xor_sync(0xffffffffu, mx0, 1));
        mx0 = fmaxf(mx0, __shfl_xor_sync(0xffffffffu, mx0, 2));
        mx1 = fmaxf(mx1, __shfl_xor_sync(0xffffffffu, mx1, 1));
        mx1 = fmaxf(mx1, __shfl_xor_sync(0xffffffffu, mx1, 2));
        float mn0 = fmaxf(mrow0, mx0), mn1 = fmaxf(mrow1, mx1);
        float al0 = __expf(mrow0 - mn0), al1 = __expf(mrow1 - mn1);
        mrow0 = mn0; mrow1 = mn1;

        uint32_t aP[4][4];
        float s0 = 0.f, s1 = 0.f;
#pragma unroll
        for (int j = 0; j < 8; ++j) {
            float p0 = __expf(sacc[j][0] - mn0);
            float p1 = __expf(sacc[j][1] - mn0);
            float p2 = __expf(sacc[j][2] - mn1);
            float p3 = __expf(sacc[j][3] - mn1);
            s0 += p0 + p1; s1 += p2 + p3;
            __half2 h01 = __floats2half2_rn(p0, p1);
            __half2 h23 = __floats2half2_rn(p2, p3);
            int ks = j >> 1, hi = (j & 1) * 2;
            aP[ks][hi]     = *(uint32_t*)&h01;
            aP[ks][hi + 1] = *(uint32_t*)&h23;
        }
        s0 += __shfl_xor_sync(0xffffffffu, s0, 1);
        s0 += __shfl_xor_sync(0xffffffffu, s0, 2);
        s1 += __shfl_xor_sync(0xffffffffu, s1, 1);
        s1 += __shfl_xor_sync(0xffffffffu, s1, 2);
        lrow0 = lrow0 * al0 + s0;
        lrow1 = lrow1 * al1 + s1;

#pragma unroll
        for (int j = 0; j < 16; ++j) {
            oacc[j][0] *= al0; oacc[j][1] *= al0;
            oacc[j][2] *= al1; oacc[j][3] *= al1;
        }

        // O += P @ V : 16 d-tiles, 4 k-steps
#pragma unroll
        for (int ks = 0; ks < 4; ++ks) {
#pragma unroll
            for (int j = 0; j < 16; ++j) {
                uint32_t bo = sV + (uint32_t)((8 * j + g) * FL_LDV + ks * 16 + 2 * tg) * 2;
                uint32_t bV[2];
                bV[0] = lds32(bo);
                bV[1] = lds32(bo + 16);
                mma_fp16(oacc[j], aP[ks], bV);
            }
        }
    }

    // Epilogue: normalize, write fp16 to g_ATh (feeds O-projection directly)
    float i0 = 1.f / lrow0, i1 = 1.f / lrow1;
    size_t row0 = qrow0 + wr + g;
#pragma unroll
    for (int j = 0; j < 16; ++j) {
        int col = h * HD + 8 * j + 2 * tg;
        *(__half2*)(g_ATh + row0 * HID + col) =
            __floats2half2_rn(oacc[j][0] * i0, oacc[j][1] * i0);
        *(__half2*)(g_ATh + (row0 + 8) * HID + col) =
            __floats2half2_rn(oacc[j][2] * i1, oacc[j][3] * i1);
    }
}

// ---------------------------------------------------------------------------
extern "C" void kernel_launch(void* const* d_in, const int* in_sizes, int n_in,
                              void* d_out, int out_size)
{
    (void)in_sizes; (void)n_in; (void)out_size;
    const float* X  = (const float*)d_in[0];
    const float* Wq = (const float*)d_in[1];
    const float* bq = (const float*)d_in[2];
    const float* Wk = (const float*)d_in[3];
    const float* bk = (const float*)d_in[4];
    const float* Wv = (const float*)d_in[5];
    const float* bv = (const float*)d_in[6];
    const float* Wo = (const float*)d_in[7];
    const float* bo = (const float*)d_in[8];
    float* out = (float*)d_out;

    (void)cudaFuncSetAttribute(flash_mma,
        cudaFuncAttributeMaxDynamicSharedMemorySize, FL_SMEM);
    (void)cudaFuncSetAttribute(qkv_mma,
        cudaFuncAttributeMaxDynamicSharedMemorySize, GSMEM);
    (void)cudaFuncSetAttribute(oproj_mma,
        cudaFuncAttributeMaxDynamicSharedMemorySize, GSMEM);

    __half *xh, *wqh, *wkh, *wvh, *woh;
    cudaGetSymbolAddress((void**)&xh,  g_Xh);
    cudaGetSymbolAddress((void**)&wqh, g_WqTh);
    cudaGetSymbolAddress((void**)&wkh, g_WkTh);
    cudaGetSymbolAddress((void**)&wvh, g_WvTh);
    cudaGetSymbolAddress((void**)&woh, g_WoTh);

    // 1) converts to fp16
    convert_rows_h<<<(MTOT * HID) / 1024, 256>>>(X, xh);
    convert_T_h<<<dim3(HID / 32, HID / 32), dim3(32, 8)>>>(Wq, wqh, HID, HID);
    convert_T_h<<<dim3(KVD / 32, HID / 32), dim3(32, 8)>>>(Wk, wkh, KVD, HID);
    convert_T_h<<<dim3(KVD / 32, HID / 32), dim3(32, 8)>>>(Wv, wvh, KVD, HID);
    convert_T_h<<<dim3(HID / 32, HID / 32), dim3(32, 8)>>>(Wo, woh, HID, HID);

    // 2) QKV projection (fp16 tensor cores)
    qkv_mma<<<dim3(20, 32), 256, GSMEM>>>(bq, bk, bv);

    // 3) attention (fp16 mma.sync flash) -> writes fp16 AT
    flash_mma<<<dim3(32, 32), 128, FL_SMEM>>>();

    // 4) O projection
    oproj_mma<<<dim3(16, 32), 256, GSMEM>>>(bo, out);
}

// round 8
// speedup vs baseline: 8.4783x; 1.9194x over previous
#include <cuda_runtime.h>
#include <cuda_fp16.h>
#include <math.h>
#include <stdint.h>

// Problem constants
#define HID   2048
#define MTOT  4096          // B*S = 2*2048
#define KVD   256           // N_KV * HEAD_DIM
#define HD    128
#define SCALING 0.08838834764831845f  // 128^-0.5

// GEMM smem geometry (fp16, 4-stage pipeline)
#define LDT    40                       // padded row length (halves); 80B rows
#define TILEB  (128 * LDT * 2)          // one 128x32 fp16 tile = 10240 B
#define STAGE  (2 * TILEB)              // A + B = 20480 B
#define GSMEM  (4 * STAGE)              // 4-stage = 81920 B

// ---------------------------------------------------------------------------
// Scratch (device globals; no runtime allocation allowed)
// ---------------------------------------------------------------------------
__device__ __half g_Qh[(size_t)MTOT * HID];
__device__ __half g_Kh[(size_t)MTOT * KVD];
__device__ __half g_Vh[(size_t)MTOT * KVD];
__device__ __half g_ATh[(size_t)MTOT * HID];

__device__ __half g_Xh[(size_t)MTOT * HID];
__device__ __half g_WqTh[(size_t)HID * HID];
__device__ __half g_WkTh[(size_t)KVD * HID];
__device__ __half g_WvTh[(size_t)KVD * HID];
__device__ __half g_WoTh[(size_t)HID * HID];

// ---------------------------------------------------------------------------
// Helpers
// ---------------------------------------------------------------------------
__device__ __forceinline__ uint32_t smem_u32(const void* p) {
    uint32_t a;
    asm("{ .reg .u64 t; cvta.to.shared.u64 t, %1; cvt.u32.u64 %0, t; }"
        : "=r"(a) : "l"(p));
    return a;
}
__device__ __forceinline__ void cp16(uint32_t sa, const void* ga) {
    asm volatile("cp.async.cg.shared.global [%0], [%1], 16;"
                 :: "r"(sa), "l"(ga) : "memory");
}
#define CP_COMMIT() asm volatile("cp.async.commit_group;" ::: "memory")

__device__ __forceinline__ void ldsm_x4(uint32_t& r0, uint32_t& r1,
                                        uint32_t& r2, uint32_t& r3, uint32_t a) {
    asm volatile("ldmatrix.sync.aligned.m8n8.x4.shared.b16 {%0,%1,%2,%3}, [%4];"
                 : "=r"(r0), "=r"(r1), "=r"(r2), "=r"(r3) : "r"(a));
}
__device__ __forceinline__ void ldsm_x4_t(uint32_t& r0, uint32_t& r1,
                                          uint32_t& r2, uint32_t& r3, uint32_t a) {
    asm volatile("ldmatrix.sync.aligned.m8n8.x4.trans.shared.b16 {%0,%1,%2,%3}, [%4];"
                 : "=r"(r0), "=r"(r1), "=r"(r2), "=r"(r3) : "r"(a));
}
__device__ __forceinline__ void mma_fp16(float* c, const uint32_t* a,
                                         const uint32_t* b) {
    asm volatile(
        "mma.sync.aligned.m16n8k16.row.col.f32.f16.f16.f32 "
        "{%0,%1,%2,%3}, {%4,%5,%6,%7}, {%8,%9}, {%0,%1,%2,%3};"
        : "+f"(c[0]), "+f"(c[1]), "+f"(c[2]), "+f"(c[3])
        : "r"(a[0]), "r"(a[1]), "r"(a[2]), "r"(a[3]), "r"(b[0]), "r"(b[1]));
}

// ---------------------------------------------------------------------------
// Converts: fp32 -> fp16
// ---------------------------------------------------------------------------
__global__ __launch_bounds__(256)
void convert_rows_h(const float* __restrict__ src, __half* __restrict__ dst)
{
    size_t i = ((size_t)blockIdx.x * 256 + threadIdx.x) * 4;
    float4 v = *(const float4*)(src + i);
    *(__half2*)(dst + i)     = __floats2half2_rn(v.x, v.y);
    *(__half2*)(dst + i + 2) = __floats2half2_rn(v.z, v.w);
}

// W [K x N] f32 -> WT [N x K] fp16. grid = (N/32, K/32), block = (32, 8)
__global__ __launch_bounds__(256)
void convert_T_h(const float* __restrict__ W, __half* __restrict__ WT,
                 int N, int K)
{
    __shared__ float tile[32][33];
    int n0 = blockIdx.x * 32, k0 = blockIdx.y * 32;
    int tx = threadIdx.x, ty = threadIdx.y;
#pragma unroll
    for (int j = 0; j < 4; ++j)
        tile[ty + 8 * j][tx] = W[(size_t)(k0 + ty + 8 * j) * N + n0 + tx];
    __syncthreads();
#pragma unroll
    for (int j = 0; j < 4; ++j) {
        int nn = n0 + ty + 8 * j;
        WT[(size_t)nn * K + k0 + tx] = __float2half_rn(tile[tx][ty + 8 * j]);
    }
}

// ---------------------------------------------------------------------------
// fp16 GEMM with ldmatrix + 4-stage cp.async. C[128x128] tile, 256 threads,
// 8 warps (2m x 4n), warp tile 64x32, K staged 32 wide.
// ---------------------------------------------------------------------------
__device__ void gemm_fp16_body(
    const __half* __restrict__ A, const __half* __restrict__ B,
    const float* __restrict__ bias, float* __restrict__ Cf,
    __half* __restrict__ Ch, int ldc, int m0, int n0, float scale, char* smb)
{
    const int t    = threadIdx.x;
    const int lane = t & 31, wid = t >> 5;
    const int wm   = wid & 1;        // 0..1 (64 rows)
    const int wn   = wid >> 1;       // 0..3 (32 cols)
    const int g    = lane >> 2;      // 0..7
    const int tg   = lane & 3;       // 0..3
    const int l15  = lane & 15, l7 = lane & 7;
    const int hi16 = lane >> 4;          // 0/1
    const int k8   = (lane >> 3) & 1;    // 0/1
    const uint32_t sb = smem_u32(smb);

    float acc[4][4][4];
#pragma unroll
    for (int im = 0; im < 4; ++im)
#pragma unroll
        for (int in = 0; in < 4; ++in)
#pragma unroll
            for (int r = 0; r < 4; ++r) acc[im][in][r] = 0.f;

    auto prefetch = [&](int s) {
        const uint32_t base = sb + (uint32_t)(s & 3) * STAGE;
        const int k0 = s * 32;
#pragma unroll
        for (int i = 0; i < 2; ++i) {
            int idx = t + 256 * i;          // 0..511
            int r = idx >> 2, c = idx & 3;  // r 0..127, c*8 halves (32 total)
            uint32_t so = base + (uint32_t)(r * LDT + c * 8) * 2;
            cp16(so,         A + (size_t)(m0 + r) * HID + k0 + c * 8);
            cp16(so + TILEB, B + (size_t)(n0 + r) * HID + k0 + c * 8);
        }
        CP_COMMIT();
    };

    prefetch(0); prefetch(1); prefetch(2);

    for (int s = 0; s < 64; ++s) {
        if (s < 62)       asm volatile("cp.async.wait_group 2;" ::: "memory");
        else if (s == 62) asm volatile("cp.async.wait_group 1;" ::: "memory");
        else              asm volatile("cp.async.wait_group 0;" ::: "memory");
        __syncthreads();
        if (s + 3 < 64) prefetch(s + 3);

        const uint32_t base = sb + (uint32_t)(s & 3) * STAGE;
#pragma unroll
        for (int kk = 0; kk < 32; kk += 16) {
            uint32_t ah[4][4], bh[4][2];
#pragma unroll
            for (int im = 0; im < 4; ++im) {
                uint32_t ao = base +
                    (uint32_t)((wm * 64 + im * 16 + l15) * LDT + kk) * 2 + hi16 * 16;
                ldsm_x4(ah[im][0], ah[im][1], ah[im][2], ah[im][3], ao);
            }
#pragma unroll
            for (int p = 0; p < 2; ++p) {
                uint32_t bo = base + TILEB +
                    (uint32_t)((wn * 32 + p * 16 + l7 + hi16 * 8) * LDT + kk) * 2 + k8 * 16;
                uint32_t r0, r1, r2, r3;
                ldsm_x4(r0, r1, r2, r3, bo);
                bh[2 * p][0] = r0;     bh[2 * p][1] = r1;
                bh[2 * p + 1][0] = r2; bh[2 * p + 1][1] = r3;
            }
#pragma unroll
            for (int im = 0; im < 4; ++im)
#pragma unroll
                for (int in = 0; in < 4; ++in)
                    mma_fp16(acc[im][in], ah[im], bh[in]);
        }
    }

    // Epilogue: + bias, * scale
#pragma unroll
    for (int im = 0; im < 4; ++im) {
#pragma unroll
        for (int in = 0; in < 4; ++in) {
            int row = m0 + wm * 64 + im * 16 + g;
            int col = n0 + wn * 32 + in * 8 + 2 * tg;
            float2 b2 = *(const float2*)(bias + col);
            float x0 = (acc[im][in][0] + b2.x) * scale;
            float x1 = (acc[im][in][1] + b2.y) * scale;
            float x2 = (acc[im][in][2] + b2.x) * scale;
            float x3 = (acc[im][in][3] + b2.y) * scale;
            if (Ch) {
                *(__half2*)(Ch + (size_t)row * ldc + col) = __floats2half2_rn(x0, x1);
                *(__half2*)(Ch + (size_t)(row + 8) * ldc + col) = __floats2half2_rn(x2, x3);
            } else {
                *(float2*)(Cf + (size_t)row * ldc + col)       = make_float2(x0, x1);
                *(float2*)(Cf + (size_t)(row + 8) * ldc + col) = make_float2(x2, x3);
            }
        }
    }
}

// Fused QKV projection. grid = (20, 32), block = 256. Outputs fp16.
__global__ __launch_bounds__(256)
void qkv_mma(const float* __restrict__ bq, const float* __restrict__ bk,
             const float* __restrict__ bv)
{
    extern __shared__ char smb[];
    int gx = blockIdx.x, m0 = blockIdx.y * 128;
    if (gx < 16) {
        gemm_fp16_body(g_Xh, g_WqTh, bq, nullptr, g_Qh, HID,
                       m0, gx * 128, SCALING, smb);
    } else if (gx < 18) {
        gemm_fp16_body(g_Xh, g_WkTh, bk, nullptr, g_Kh, KVD,
                       m0, (gx - 16) * 128, 1.f, smb);
    } else {
        gemm_fp16_body(g_Xh, g_WvTh, bv, nullptr, g_Vh, KVD,
                       m0, (gx - 18) * 128, 1.f, smb);
    }
}

// O projection. grid = (16, 32), block = 256. Outputs fp32.
__global__ __launch_bounds__(256)
void oproj_mma(const float* __restrict__ bo, float* __restrict__ out)
{
    extern __shared__ char smb[];
    gemm_fp16_body(g_ATh, g_WoTh, bo, out, nullptr, HID,
                   blockIdx.y * 128, blockIdx.x * 128, 1.f, smb);
}

// ---------------------------------------------------------------------------
// Flash attention, fp16 mma.sync + ldmatrix(+trans) + cp.async dbuf K/V.
// grid = (32 qblocks, 32 bh), 128 threads, Br=64, Bc=64, D=128.
// smem: Q[64][136], K0,K1,V0,V1 each [64][136]  (K/V in [token][d] layout).
// ---------------------------------------------------------------------------
#define FL_LDK  136
#define FL_TILE (64 * FL_LDK * 2)        // 17408 B
#define FL_SMEM (5 * FL_TILE)            // 87040 B

__global__ __launch_bounds__(128, 2)
void flash_mma()
{
    extern __shared__ __half fsm[];
    const uint32_t sQ  = smem_u32(fsm);
    const uint32_t sK0 = sQ + FL_TILE;       // K bufs
    const uint32_t sV0 = sQ + 3 * FL_TILE;   // V bufs

    const int t = threadIdx.x, lane = t & 31, warp = t >> 5;
    const int g = lane >> 2, tg = lane & 3;
    const int l15 = lane & 15, l7 = lane & 7;
    const int hi16 = lane >> 4, k8 = (lane >> 3) & 1;
    const int bh = blockIdx.y, b = bh >> 4, h = bh & 15, kvh = h >> 3;
    const int q0 = blockIdx.x * 64;
    const size_t qrow0 = (size_t)(b * 2048 + q0);
    const int wr = warp * 16;

    // Tile = 64 rows x 128 halves = 1024 16B chunks per array.
    auto prefetch_kv = [&](int kb) {
        const uint32_t buf = (uint32_t)(kb & 1) * FL_TILE;
        const size_t krow0 = (size_t)(b * 2048 + kb * 64);
#pragma unroll
        for (int s = 0; s < 8; ++s) {
            int i = t + 128 * s;             // 0..1023
            int r = i >> 4, c = i & 15;      // r 0..63, c*8 halves (128 total)
            uint32_t so = (uint32_t)(r * FL_LDK + c * 8) * 2;
            size_t go = (krow0 + r) * KVD + kvh * HD + c * 8;
            cp16(sK0 + buf + so, g_Kh + go);
            cp16(sV0 + buf + so, g_Vh + go);
        }
        CP_COMMIT();
    };

    prefetch_kv(0);

    // Stage Q tile 64x128 fp16 (full row coverage: 16 chunks per row)
#pragma unroll
    for (int s = 0; s < 8; ++s) {
        int i = t + 128 * s;
        int r = i >> 4, c = i & 15;
        *(uint4*)(fsm + r * FL_LDK + c * 8) =
            *(const uint4*)(g_Qh + (qrow0 + r) * HID + h * HD + c * 8);
    }
    __syncthreads();

    // Q fragments via ldmatrix: 8 k-steps
    uint32_t aQ[8][4];
#pragma unroll
    for (int ks = 0; ks < 8; ++ks) {
        uint32_t ao = sQ + (uint32_t)((wr + l15) * FL_LDK + ks * 16) * 2 + hi16 * 16;
        ldsm_x4(aQ[ks][0], aQ[ks][1], aQ[ks][2], aQ[ks][3], ao);
    }

    float oacc[16][4];
#pragma unroll
    for (int j = 0; j < 16; ++j)
#pragma unroll
        for (int r = 0; r < 4; ++r) oacc[j][r] = 0.f;
    float mrow0 = -1e30f, mrow1 = -1e30f, lrow0 = 0.f, lrow1 = 0.f;

    for (int kb = 0; kb < 32; ++kb) {
        asm volatile("cp.async.wait_group 0;" ::: "memory");
        __syncthreads();
        if (kb + 1 < 32) prefetch_kv(kb + 1);

        const uint32_t sK = sK0 + (uint32_t)(kb & 1) * FL_TILE;
        const uint32_t sV = sV0 + (uint32_t)(kb & 1) * FL_TILE;

        // S = Q @ K^T : 8 n8-tiles
        float sacc[8][4];
#pragma unroll
        for (int j = 0; j < 8; ++j)
#pragma unroll
            for (int r = 0; r < 4; ++r) sacc[j][r] = 0.f;
#pragma unroll
        for (int ks = 0; ks < 8; ++ks) {
#pragma unroll
            for (int p = 0; p < 4; ++p) {
                uint32_t bo = sK +
                    (uint32_t)((p * 16 + l7 + hi16 * 8) * FL_LDK + ks * 16) * 2 + k8 * 16;
                uint32_t r0, r1, r2, r3;
                ldsm_x4(r0, r1, r2, r3, bo);
                uint32_t b0[2] = {r0, r1}, b1[2] = {r2, r3};
                mma_fp16(sacc[2 * p], aQ[ks], b0);
                mma_fp16(sacc[2 * p + 1], aQ[ks], b1);
            }
        }

        // Online softmax (rows g and g+8 of warp tile)
        float mx0 = -1e30f, mx1 = -1e30f;
#pragma unroll
        for (int j = 0; j < 8; ++j) {
            mx0 = fmaxf(mx0, fmaxf(sacc[j][0], sacc[j][1]));
            mx1 = fmaxf(mx1, fmaxf(sacc[j][2], sacc[j][3]));
        }
        mx0 = fmaxf(mx0, __shfl_xor_sync(0xffffffffu, mx0, 1));
        mx0 = fmaxf(mx0, __shfl_xor_sync(0xffffffffu, mx0, 2));
        mx1 = fmaxf(mx1, __shfl_xor_sync(0xffffffffu, mx1, 1));
        mx1 = fmaxf(mx1, __shfl_xor_sync(0xffffffffu, mx1, 2));
        float mn0 = fmaxf(mrow0, mx0), mn1 = fmaxf(mrow1, mx1);
        float al0 = __expf(mrow0 - mn0), al1 = __expf(mrow1 - mn1);
        mrow0 = mn0; mrow1 = mn1;

        uint32_t aP[4][4];
        float s0 = 0.f, s1 = 0.f;
#pragma unroll
        for (int j = 0; j < 8; ++j) {
            float p0 = __expf(sacc[j][0] - mn0);
            float p1 = __expf(sacc[j][1] - mn0);
            float p2 = __expf(sacc[j][2] - mn1);
            float p3 = __expf(sacc[j][3] - mn1);
            s0 += p0 + p1; s1 += p2 + p3;
            __half2 h01 = __floats2half2_rn(p0, p1);
            __half2 h23 = __floats2half2_rn(p2, p3);
            int ks = j >> 1, hi = (j & 1) * 2;
            aP[ks][hi]     = *(uint32_t*)&h01;
            aP[ks][hi + 1] = *(uint32_t*)&h23;
        }
        s0 += __shfl_xor_sync(0xffffffffu, s0, 1);
        s0 += __shfl_xor_sync(0xffffffffu, s0, 2);
        s1 += __shfl_xor_sync(0xffffffffu, s1, 1);
        s1 += __shfl_xor_sync(0xffffffffu, s1, 2);
        lrow0 = lrow0 * al0 + s0;
        lrow1 = lrow1 * al1 + s1;

#pragma unroll
        for (int j = 0; j < 16; ++j) {
            oacc[j][0] *= al0; oacc[j][1] *= al0;
            oacc[j][2] *= al1; oacc[j][3] *= al1;
        }

        // O += P @ V : 16 d-tiles, V fragments via ldmatrix.trans
#pragma unroll
        for (int ks = 0; ks < 4; ++ks) {
#pragma unroll
            for (int p = 0; p < 8; ++p) {
                uint32_t vo = sV +
                    (uint32_t)((ks * 16 + l7 + k8 * 8) * FL_LDK) * 2 + (2 * p + hi16) * 16;
                uint32_t r0, r1, r2, r3;
                ldsm_x4_t(r0, r1, r2, r3, vo);
                uint32_t b0[2] = {r0, r1}, b1[2] = {r2, r3};
                mma_fp16(oacc[2 * p], aP[ks], b0);
                mma_fp16(oacc[2 * p + 1], aP[ks], b1);
            }
        }
    }

    // Epilogue: normalize, write fp16 to g_ATh
    float i0 = 1.f / lrow0, i1 = 1.f / lrow1;
    size_t row0 = qrow0 + wr + g;
#pragma unroll
    for (int j = 0; j < 16; ++j) {
        int col = h * HD + 8 * j + 2 * tg;
        *(__half2*)(g_ATh + row0 * HID + col) =
            __floats2half2_rn(oacc[j][0] * i0, oacc[j][1] * i0);
        *(__half2*)(g_ATh + (row0 + 8) * HID + col) =
            __floats2half2_rn(oacc[j][2] * i1, oacc[j][3] * i1);
    }
}

// ---------------------------------------------------------------------------
extern "C" void kernel_launch(void* const* d_in, const int* in_sizes, int n_in,
                              void* d_out, int out_size)
{
    (void)in_sizes; (void)n_in; (void)out_size;
    const float* X  = (const float*)d_in[0];
    const float* Wq = (const float*)d_in[1];
    const float* bq = (const float*)d_in[2];
    const float* Wk = (const float*)d_in[3];
    const float* bk = (const float*)d_in[4];
    const float* Wv = (const float*)d_in[5];
    const float* bv = (const float*)d_in[6];
    const float* Wo = (const float*)d_in[7];
    const float* bo = (const float*)d_in[8];
    float* out = (float*)d_out;

    (void)cudaFuncSetAttribute(flash_mma,
        cudaFuncAttributeMaxDynamicSharedMemorySize, FL_SMEM);
    (void)cudaFuncSetAttribute(qkv_mma,
        cudaFuncAttributeMaxDynamicSharedMemorySize, GSMEM);
    (void)cudaFuncSetAttribute(oproj_mma,
        cudaFuncAttributeMaxDynamicSharedMemorySize, GSMEM);

    __half *xh, *wqh, *wkh, *wvh, *woh;
    cudaGetSymbolAddress((void**)&xh,  g_Xh);
    cudaGetSymbolAddress((void**)&wqh, g_WqTh);
    cudaGetSymbolAddress((void**)&wkh, g_WkTh);
    cudaGetSymbolAddress((void**)&wvh, g_WvTh);
    cudaGetSymbolAddress((void**)&woh, g_WoTh);

    // 1) converts to fp16
    convert_rows_h<<<(MTOT * HID) / 1024, 256>>>(X, xh);
    convert_T_h<<<dim3(HID / 32, HID / 32), dim3(32, 8)>>>(Wq, wqh, HID, HID);
    convert_T_h<<<dim3(KVD / 32, HID / 32), dim3(32, 8)>>>(Wk, wkh, KVD, HID);
    convert_T_h<<<dim3(KVD / 32, HID / 32), dim3(32, 8)>>>(Wv, wvh, KVD, HID);
    convert_T_h<<<dim3(HID / 32, HID / 32), dim3(32, 8)>>>(Wo, woh, HID, HID);

    // 2) QKV projection (fp16 tensor cores)
    qkv_mma<<<dim3(20, 32), 256, GSMEM>>>(bq, bk, bv);

    // 3) attention (fp16 mma.sync flash)
    flash_mma<<<dim3(32, 32), 128, FL_SMEM>>>();

    // 4) O projection
    oproj_mma<<<dim3(16, 32), 256, GSMEM>>>(bo, out);
}

// round 10
// speedup vs baseline: 9.1377x; 1.0778x over previous
#include <cuda_runtime.h>
#include <cuda_fp16.h>
#include <math.h>
#include <stdint.h>

// Problem constants
#define HID   2048
#define MTOT  4096          // B*S = 2*2048
#define KVD   256           // N_KV * HEAD_DIM
#define HD    128
#define SCALING 0.08838834764831845f  // 128^-0.5

// GEMM smem geometry (fp16, 4-stage pipeline)
#define LDT    40                       // padded row length (halves); 80B rows
#define TILEB  (128 * LDT * 2)          // one 128x32 fp16 tile = 10240 B
#define STAGE  (2 * TILEB)              // A + B = 20480 B
#define GSMEM  (4 * STAGE)              // 4-stage = 81920 B

// ---------------------------------------------------------------------------
// Scratch (device globals; no runtime allocation allowed)
// ---------------------------------------------------------------------------
__device__ __half g_Qh[(size_t)MTOT * HID];
__device__ __half g_Kh[(size_t)MTOT * KVD];
__device__ __half g_Vh[(size_t)MTOT * KVD];
__device__ __half g_ATh[(size_t)MTOT * HID];

__device__ __half g_Xh[(size_t)MTOT * HID];
__device__ __half g_WqTh[(size_t)HID * HID];
__device__ __half g_WkTh[(size_t)KVD * HID];
__device__ __half g_WvTh[(size_t)KVD * HID];
__device__ __half g_WoTh[(size_t)HID * HID];

// ---------------------------------------------------------------------------
// Helpers
// ---------------------------------------------------------------------------
__device__ __forceinline__ uint32_t smem_u32(const void* p) {
    uint32_t a;
    asm("{ .reg .u64 t; cvta.to.shared.u64 t, %1; cvt.u32.u64 %0, t; }"
        : "=r"(a) : "l"(p));
    return a;
}
__device__ __forceinline__ void cp16(uint32_t sa, const void* ga) {
    asm volatile("cp.async.cg.shared.global [%0], [%1], 16;"
                 :: "r"(sa), "l"(ga) : "memory");
}
#define CP_COMMIT() asm volatile("cp.async.commit_group;" ::: "memory")

__device__ __forceinline__ void ldsm_x4(uint32_t& r0, uint32_t& r1,
                                        uint32_t& r2, uint32_t& r3, uint32_t a) {
    asm volatile("ldmatrix.sync.aligned.m8n8.x4.shared.b16 {%0,%1,%2,%3}, [%4];"
                 : "=r"(r0), "=r"(r1), "=r"(r2), "=r"(r3) : "r"(a));
}
__device__ __forceinline__ void ldsm_x4_t(uint32_t& r0, uint32_t& r1,
                                          uint32_t& r2, uint32_t& r3, uint32_t a) {
    asm volatile("ldmatrix.sync.aligned.m8n8.x4.trans.shared.b16 {%0,%1,%2,%3}, [%4];"
                 : "=r"(r0), "=r"(r1), "=r"(r2), "=r"(r3) : "r"(a));
}
__device__ __forceinline__ void mma_fp16(float* c, const uint32_t* a,
                                         const uint32_t* b) {
    asm volatile(
        "mma.sync.aligned.m16n8k16.row.col.f32.f16.f16.f32 "
        "{%0,%1,%2,%3}, {%4,%5,%6,%7}, {%8,%9}, {%0,%1,%2,%3};"
        : "+f"(c[0]), "+f"(c[1]), "+f"(c[2]), "+f"(c[3])
        : "r"(a[0]), "r"(a[1]), "r"(a[2]), "r"(a[3]), "r"(b[0]), "r"(b[1]));
}

// ---------------------------------------------------------------------------
// Converts: fp32 -> fp16
// ---------------------------------------------------------------------------
__global__ __launch_bounds__(256)
void convert_rows_h(const float* __restrict__ src, __half* __restrict__ dst)
{
    size_t i = ((size_t)blockIdx.x * 256 + threadIdx.x) * 4;
    float4 v = *(const float4*)(src + i);
    *(__half2*)(dst + i)     = __floats2half2_rn(v.x, v.y);
    *(__half2*)(dst + i + 2) = __floats2half2_rn(v.z, v.w);
}

// W [K x N] f32 -> WT [N x K] fp16. grid = (N/32, K/32), block = (32, 8)
__global__ __launch_bounds__(256)
void convert_T_h(const float* __restrict__ W, __half* __restrict__ WT,
                 int N, int K)
{
    __shared__ float tile[32][33];
    int n0 = blockIdx.x * 32, k0 = blockIdx.y * 32;
    int tx = threadIdx.x, ty = threadIdx.y;
#pragma unroll
    for (int j = 0; j < 4; ++j)
        tile[ty + 8 * j][tx] = W[(size_t)(k0 + ty + 8 * j) * N + n0 + tx];
    __syncthreads();
#pragma unroll
    for (int j = 0; j < 4; ++j) {
        int nn = n0 + ty + 8 * j;
        WT[(size_t)nn * K + k0 + tx] = __float2half_rn(tile[tx][ty + 8 * j]);
    }
}

// ---------------------------------------------------------------------------
// fp16 GEMM v2: 128 threads, 4 warps (2m x 2n), warp tile 64x64.
// CTA tile 128x128, K staged 32 wide, 4-stage cp.async, ldmatrix frags.
// ---------------------------------------------------------------------------
__device__ void gemm_fp16_body(
    const __half* __restrict__ A, const __half* __restrict__ B,
    const float* __restrict__ bias, float* __restrict__ Cf,
    __half* __restrict__ Ch, int ldc, int m0, int n0, float scale, char* smb)
{
    const int t    = threadIdx.x;                 // 0..127
    const int lane = t & 31, wid = t >> 5;        // 4 warps
    const int wm   = wid & 1;        // 0..1 (64-row half)
    const int wn   = wid >> 1;       // 0..1 (64-col half)
    const int g    = lane >> 2;      // 0..7
    const int tg   = lane & 3;       // 0..3
    const int l15  = lane & 15, l7 = lane & 7;
    const int hi16 = lane >> 4;          // 0/1
    const int k8   = (lane >> 3) & 1;    // 0/1
    const uint32_t sb = smem_u32(smb);

    float acc[4][8][4];
#pragma unroll
    for (int im = 0; im < 4; ++im)
#pragma unroll
        for (int in = 0; in < 8; ++in)
#pragma unroll
            for (int r = 0; r < 4; ++r) acc[im][in][r] = 0.f;

    auto prefetch = [&](int s) {
        const uint32_t base = sb + (uint32_t)(s & 3) * STAGE;
        const int k0 = s * 32;
#pragma unroll
        for (int i = 0; i < 4; ++i) {
            int idx = t + 128 * i;          // 0..511
            int r = idx >> 2, c = idx & 3;  // r 0..127, c*8 halves (32 total)
            uint32_t so = base + (uint32_t)(r * LDT + c * 8) * 2;
            cp16(so,         A + (size_t)(m0 + r) * HID + k0 + c * 8);
            cp16(so + TILEB, B + (size_t)(n0 + r) * HID + k0 + c * 8);
        }
        CP_COMMIT();
    };

    prefetch(0); prefetch(1); prefetch(2);

    for (int s = 0; s < 64; ++s) {
        if (s < 62)       asm volatile("cp.async.wait_group 2;" ::: "memory");
        else if (s == 62) asm volatile("cp.async.wait_group 1;" ::: "memory");
        else              asm volatile("cp.async.wait_group 0;" ::: "memory");
        __syncthreads();
        if (s + 3 < 64) prefetch(s + 3);

        const uint32_t base = sb + (uint32_t)(s & 3) * STAGE;
#pragma unroll
        for (int kk = 0; kk < 32; kk += 16) {
            uint32_t ah[4][4], bh[8][2];
#pragma unroll
            for (int im = 0; im < 4; ++im) {
                uint32_t ao = base +
                    (uint32_t)((wm * 64 + im * 16 + l15) * LDT + kk) * 2 + hi16 * 16;
                ldsm_x4(ah[im][0], ah[im][1], ah[im][2], ah[im][3], ao);
            }
#pragma unroll
            for (int p = 0; p < 4; ++p) {
                uint32_t bo = base + TILEB +
                    (uint32_t)((wn * 64 + p * 16 + l7 + hi16 * 8) * LDT + kk) * 2 + k8 * 16;
                uint32_t r0, r1, r2, r3;
                ldsm_x4(r0, r1, r2, r3, bo);
                bh[2 * p][0] = r0;     bh[2 * p][1] = r1;
                bh[2 * p + 1][0] = r2; bh[2 * p + 1][1] = r3;
            }
#pragma unroll
            for (int im = 0; im < 4; ++im)
#pragma unroll
                for (int in = 0; in < 8; ++in)
                    mma_fp16(acc[im][in], ah[im], bh[in]);
        }
    }

    // Epilogue: + bias, * scale
#pragma unroll
    for (int im = 0; im < 4; ++im) {
#pragma unroll
        for (int in = 0; in < 8; ++in) {
            int row = m0 + wm * 64 + im * 16 + g;
            int col = n0 + wn * 64 + in * 8 + 2 * tg;
            float2 b2 = *(const float2*)(bias + col);
            float x0 = (acc[im][in][0] + b2.x) * scale;
            float x1 = (acc[im][in][1] + b2.y) * scale;
            float x2 = (acc[im][in][2] + b2.x) * scale;
            float x3 = (acc[im][in][3] + b2.y) * scale;
            if (Ch) {
                *(__half2*)(Ch + (size_t)row * ldc + col) = __floats2half2_rn(x0, x1);
                *(__half2*)(Ch + (size_t)(row + 8) * ldc + col) = __floats2half2_rn(x2, x3);
            } else {
                *(float2*)(Cf + (size_t)row * ldc + col)       = make_float2(x0, x1);
                *(float2*)(Cf + (size_t)(row + 8) * ldc + col) = make_float2(x2, x3);
            }
        }
    }
}

// Fused QKV projection. grid = (20, 32), block = 128. Outputs fp16.
__global__ __launch_bounds__(128, 2)
void qkv_mma(const float* __restrict__ bq, const float* __restrict__ bk,
             const float* __restrict__ bv)
{
    extern __shared__ char smb[];
    int gx = blockIdx.x, m0 = blockIdx.y * 128;
    if (gx < 16) {
        gemm_fp16_body(g_Xh, g_WqTh, bq, nullptr, g_Qh, HID,
                       m0, gx * 128, SCALING, smb);
    } else if (gx < 18) {
        gemm_fp16_body(g_Xh, g_WkTh, bk, nullptr, g_Kh, KVD,
                       m0, (gx - 16) * 128, 1.f, smb);
    } else {
        gemm_fp16_body(g_Xh, g_WvTh, bv, nullptr, g_Vh, KVD,
                       m0, (gx - 18) * 128, 1.f, smb);
    }
}

// O projection. grid = (16, 32), block = 128. Outputs fp32.
__global__ __launch_bounds__(128, 2)
void oproj_mma(const float* __restrict__ bo, float* __restrict__ out)
{
    extern __shared__ char smb[];
    gemm_fp16_body(g_ATh, g_WoTh, bo, out, nullptr, HID,
                   blockIdx.y * 128, blockIdx.x * 128, 1.f, smb);
}

// ---------------------------------------------------------------------------
// Flash attention (unchanged from round 8 — proven).
// grid = (32 qblocks, 32 bh), 128 threads, Br=64, Bc=64, D=128.
// ---------------------------------------------------------------------------
#define FL_LDK  136
#define FL_TILE (64 * FL_LDK * 2)        // 17408 B
#define FL_SMEM (5 * FL_TILE)            // 87040 B

__global__ __launch_bounds__(128, 2)
void flash_mma()
{
    extern __shared__ __half fsm[];
    const uint32_t sQ  = smem_u32(fsm);
    const uint32_t sK0 = sQ + FL_TILE;       // K bufs
    const uint32_t sV0 = sQ + 3 * FL_TILE;   // V bufs

    const int t = threadIdx.x, lane = t & 31, warp = t >> 5;
    const int g = lane >> 2, tg = lane & 3;
    const int l15 = lane & 15, l7 = lane & 7;
    const int hi16 = lane >> 4, k8 = (lane >> 3) & 1;
    const int bh = blockIdx.y, b = bh >> 4, h = bh & 15, kvh = h >> 3;
    const int q0 = blockIdx.x * 64;
    const size_t qrow0 = (size_t)(b * 2048 + q0);
    const int wr = warp * 16;

    auto prefetch_kv = [&](int kb) {
        const uint32_t buf = (uint32_t)(kb & 1) * FL_TILE;
        const size_t krow0 = (size_t)(b * 2048 + kb * 64);
#pragma unroll
        for (int s = 0; s < 8; ++s) {
            int i = t + 128 * s;             // 0..1023
            int r = i >> 4, c = i & 15;      // r 0..63, c*8 halves (128 total)
            uint32_t so = (uint32_t)(r * FL_LDK + c * 8) * 2;
            size_t go = (krow0 + r) * KVD + kvh * HD + c * 8;
            cp16(sK0 + buf + so, g_Kh + go);
            cp16(sV0 + buf + so, g_Vh + go);
        }
        CP_COMMIT();
    };

    prefetch_kv(0);

    // Stage Q tile 64x128 fp16
#pragma unroll
    for (int s = 0; s < 8; ++s) {
        int i = t + 128 * s;
        int r = i >> 4, c = i & 15;
        *(uint4*)(fsm + r * FL_LDK + c * 8) =
            *(const uint4*)(g_Qh + (qrow0 + r) * HID + h * HD + c * 8);
    }
    __syncthreads();

    // Q fragments via ldmatrix: 8 k-steps
    uint32_t aQ[8][4];
#pragma unroll
    for (int ks = 0; ks < 8; ++ks) {
        uint32_t ao = sQ + (uint32_t)((wr + l15) * FL_LDK + ks * 16) * 2 + hi16 * 16;
        ldsm_x4(aQ[ks][0], aQ[ks][1], aQ[ks][2], aQ[ks][3], ao);
    }

    float oacc[16][4];
#pragma unroll
    for (int j = 0; j < 16; ++j)
#pragma unroll
        for (int r = 0; r < 4; ++r) oacc[j][r] = 0.f;
    float mrow0 = -1e30f, mrow1 = -1e30f, lrow0 = 0.f, lrow1 = 0.f;

    for (int kb = 0; kb < 32; ++kb) {
        asm volatile("cp.async.wait_group 0;" ::: "memory");
        __syncthreads();
        if (kb + 1 < 32) prefetch_kv(kb + 1);

        const uint32_t sK = sK0 + (uint32_t)(kb & 1) * FL_TILE;
        const uint32_t sV = sV0 + (uint32_t)(kb & 1) * FL_TILE;

        // S = Q @ K^T : 8 n8-tiles
        float sacc[8][4];
#pragma unroll
        for (int j = 0; j < 8; ++j)
#pragma unroll
            for (int r = 0; r < 4; ++r) sacc[j][r] = 0.f;
#pragma unroll
        for (int ks = 0; ks < 8; ++ks) {
#pragma unroll
            for (int p = 0; p < 4; ++p) {
                uint32_t bo = sK +
                    (uint32_t)((p * 16 + l7 + hi16 * 8) * FL_LDK + ks * 16) * 2 + k8 * 16;
                uint32_t r0, r1, r2, r3;
                ldsm_x4(r0, r1, r2, r3, bo);
                uint32_t b0[2] = {r0, r1}, b1[2] = {r2, r3};
                mma_fp16(sacc[2 * p], aQ[ks], b0);
                mma_fp16(sacc[2 * p + 1], aQ[ks], b1);
            }
        }

        // Online softmax (rows g and g+8 of warp tile)
        float mx0 = -1e30f, mx1 = -1e30f;
#pragma unroll
        for (int j = 0; j < 8; ++j) {
            mx0 = fmaxf(mx0, fmaxf(sacc[j][0], sacc[j][1]));
            mx1 = fmaxf(mx1, fmaxf(sacc[j][2], sacc[j][3]));
        }
        mx0 = fmaxf(mx0, __shfl_xor_sync(0xffffffffu, mx0, 1));
        mx0 = fmaxf(mx0, __shfl_xor_sync(0xffffffffu, mx0, 2));
        mx1 = fmaxf(mx1, __shfl_xor_sync(0xffffffffu, mx1, 1));
        mx1 = fmaxf(mx1, __shfl_xor_sync(0xffffffffu, mx1, 2));
        float mn0 = fmaxf(mrow0, mx0), mn1 = fmaxf(mrow1, mx1);
        float al0 = __expf(mrow0 - mn0), al1 = __expf(mrow1 - mn1);
        mrow0 = mn0; mrow1 = mn1;

        uint32_t aP[4][4];
        float s0 = 0.f, s1 = 0.f;
#pragma unroll
        for (int j = 0; j < 8; ++j) {
            float p0 = __expf(sacc[j][0] - mn0);
            float p1 = __expf(sacc[j][1] - mn0);
            float p2 = __expf(sacc[j][2] - mn1);
            float p3 = __expf(sacc[j][3] - mn1);
            s0 += p0 + p1; s1 += p2 + p3;
            __half2 h01 = __floats2half2_rn(p0, p1);
            __half2 h23 = __floats2half2_rn(p2, p3);
            int ks = j >> 1, hi = (j & 1) * 2;
            aP[ks][hi]     = *(uint32_t*)&h01;
            aP[ks][hi + 1] = *(uint32_t*)&h23;
        }
        s0 += __shfl_xor_sync(0xffffffffu, s0, 1);
        s0 += __shfl_xor_sync(0xffffffffu, s0, 2);
        s1 += __shfl_xor_sync(0xffffffffu, s1, 1);
        s1 += __shfl_xor_sync(0xffffffffu, s1, 2);
        lrow0 = lrow0 * al0 + s0;
        lrow1 = lrow1 * al1 + s1;

#pragma unroll
        for (int j = 0; j < 16; ++j) {
            oacc[j][0] *= al0; oacc[j][1] *= al0;
            oacc[j][2] *= al1; oacc[j][3] *= al1;
        }

        // O += P @ V : 16 d-tiles, V fragments via ldmatrix.trans
#pragma unroll
        for (int ks = 0; ks < 4; ++ks) {
#pragma unroll
            for (int p = 0; p < 8; ++p) {
                uint32_t vo = sV +
                    (uint32_t)((ks * 16 + l7 + k8 * 8) * FL_LDK) * 2 + (2 * p + hi16) * 16;
                uint32_t r0, r1, r2, r3;
                ldsm_x4_t(r0, r1, r2, r3, vo);
                uint32_t b0[2] = {r0, r1}, b1[2] = {r2, r3};
                mma_fp16(oacc[2 * p], aP[ks], b0);
                mma_fp16(oacc[2 * p + 1], aP[ks], b1);
            }
        }
    }

    // Epilogue: normalize, write fp16 to g_ATh
    float i0 = 1.f / lrow0, i1 = 1.f / lrow1;
    size_t row0 = qrow0 + wr + g;
#pragma unroll
    for (int j = 0; j < 16; ++j) {
        int col = h * HD + 8 * j + 2 * tg;
        *(__half2*)(g_ATh + row0 * HID + col) =
            __floats2half2_rn(oacc[j][0] * i0, oacc[j][1] * i0);
        *(__half2*)(g_ATh + (row0 + 8) * HID + col) =
            __floats2half2_rn(oacc[j][2] * i1, oacc[j][3] * i1);
    }
}

// ---------------------------------------------------------------------------
extern "C" void kernel_launch(void* const* d_in, const int* in_sizes, int n_in,
                              void* d_out, int out_size)
{
    (void)in_sizes; (void)n_in; (void)out_size;
    const float* X  = (const float*)d_in[0];
    const float* Wq = (const float*)d_in[1];
    const float* bq = (const float*)d_in[2];
    const float* Wk = (const float*)d_in[3];
    const float* bk = (const float*)d_in[4];
    const float* Wv = (const float*)d_in[5];
    const float* bv = (const float*)d_in[6];
    const float* Wo = (const float*)d_in[7];
    const float* bo = (const float*)d_in[8];
    float* out = (float*)d_out;

    (void)cudaFuncSetAttribute(flash_mma,
        cudaFuncAttributeMaxDynamicSharedMemorySize, FL_SMEM);
    (void)cudaFuncSetAttribute(qkv_mma,
        cudaFuncAttributeMaxDynamicSharedMemorySize, GSMEM);
    (void)cudaFuncSetAttribute(oproj_mma,
        cudaFuncAttributeMaxDynamicSharedMemorySize, GSMEM);

    __half *xh, *wqh, *wkh, *wvh, *woh;
    cudaGetSymbolAddress((void**)&xh,  g_Xh);
    cudaGetSymbolAddress((void**)&wqh, g_WqTh);
    cudaGetSymbolAddress((void**)&wkh, g_WkTh);
    cudaGetSymbolAddress((void**)&wvh, g_WvTh);
    cudaGetSymbolAddress((void**)&woh, g_WoTh);

    // 1) converts to fp16
    convert_rows_h<<<(MTOT * HID) / 1024, 256>>>(X, xh);
    convert_T_h<<<dim3(HID / 32, HID / 32), dim3(32, 8)>>>(Wq, wqh, HID, HID);
    convert_T_h<<<dim3(KVD / 32, HID / 32), dim3(32, 8)>>>(Wk, wkh, KVD, HID);
    convert_T_h<<<dim3(KVD / 32, HID / 32), dim3(32, 8)>>>(Wv, wvh, KVD, HID);
    convert_T_h<<<dim3(HID / 32, HID / 32), dim3(32, 8)>>>(Wo, woh, HID, HID);

    // 2) QKV projection (fp16 tensor cores, v2 GEMM)
    qkv_mma<<<dim3(20, 32), 128, GSMEM>>>(bq, bk, bv);

    // 3) attention (fp16 mma.sync flash)
    flash_mma<<<dim3(32, 32), 128, FL_SMEM>>>();

    // 4) O projection
    oproj_mma<<<dim3(16, 32), 128, GSMEM>>>(bo, out);
}

// round 11
// speedup vs baseline: 9.2411x; 1.0113x over previous
#include <cuda_runtime.h>
#include <cuda_fp16.h>
#include <math.h>
#include <stdint.h>

// Problem constants
#define HID   2048
#define MTOT  4096          // B*S = 2*2048
#define KVD   256           // N_KV * HEAD_DIM
#define HD    128
#define SCALING 0.08838834764831845f  // 128^-0.5

// GEMM smem geometry, 128x128 path (oproj)
#define LDT    40                       // padded row length (halves); 80B rows
#define TILEB  (128 * LDT * 2)          // one 128x32 fp16 tile = 10240 B
#define STAGE  (2 * TILEB)              // A + B = 20480 B
#define GSMEM  (4 * STAGE)              // 4-stage = 81920 B

// GEMM smem geometry, 64x128 path (qkv, 3 CTAs/SM)
#define ATILE64 (64 * LDT * 2)          // 5120 B
#define BTILE64 (128 * LDT * 2)         // 10240 B
#define STAGE64 (ATILE64 + BTILE64)     // 15360 B
#define GSMEM64 (4 * STAGE64)           // 61440 B

// ---------------------------------------------------------------------------
// Scratch (device globals; no runtime allocation allowed)
// ---------------------------------------------------------------------------
__device__ __half g_Qh[(size_t)MTOT * HID];
__device__ __half g_Kh[(size_t)MTOT * KVD];
__device__ __half g_Vh[(size_t)MTOT * KVD];
__device__ __half g_ATh[(size_t)MTOT * HID];

__device__ __half g_Xh[(size_t)MTOT * HID];
__device__ __half g_WqTh[(size_t)HID * HID];
__device__ __half g_WkTh[(size_t)KVD * HID];
__device__ __half g_WvTh[(size_t)KVD * HID];
__device__ __half g_WoTh[(size_t)HID * HID];

// ---------------------------------------------------------------------------
// Helpers
// ---------------------------------------------------------------------------
__device__ __forceinline__ uint32_t smem_u32(const void* p) {
    uint32_t a;
    asm("{ .reg .u64 t; cvta.to.shared.u64 t, %1; cvt.u32.u64 %0, t; }"
        : "=r"(a) : "l"(p));
    return a;
}
__device__ __forceinline__ void cp16(uint32_t sa, const void* ga) {
    asm volatile("cp.async.cg.shared.global [%0], [%1], 16;"
                 :: "r"(sa), "l"(ga) : "memory");
}
#define CP_COMMIT() asm volatile("cp.async.commit_group;" ::: "memory")

__device__ __forceinline__ void ldsm_x4(uint32_t& r0, uint32_t& r1,
                                        uint32_t& r2, uint32_t& r3, uint32_t a) {
    asm volatile("ldmatrix.sync.aligned.m8n8.x4.shared.b16 {%0,%1,%2,%3}, [%4];"
                 : "=r"(r0), "=r"(r1), "=r"(r2), "=r"(r3) : "r"(a));
}
__device__ __forceinline__ void ldsm_x4_t(uint32_t& r0, uint32_t& r1,
                                          uint32_t& r2, uint32_t& r3, uint32_t a) {
    asm volatile("ldmatrix.sync.aligned.m8n8.x4.trans.shared.b16 {%0,%1,%2,%3}, [%4];"
                 : "=r"(r0), "=r"(r1), "=r"(r2), "=r"(r3) : "r"(a));
}
__device__ __forceinline__ void mma_fp16(float* c, const uint32_t* a,
                                         const uint32_t* b) {
    asm volatile(
        "mma.sync.aligned.m16n8k16.row.col.f32.f16.f16.f32 "
        "{%0,%1,%2,%3}, {%4,%5,%6,%7}, {%8,%9}, {%0,%1,%2,%3};"
        : "+f"(c[0]), "+f"(c[1]), "+f"(c[2]), "+f"(c[3])
        : "r"(a[0]), "r"(a[1]), "r"(a[2]), "r"(a[3]), "r"(b[0]), "r"(b[1]));
}

// ---------------------------------------------------------------------------
// Merged converts: fp32 -> fp16 (X rows + 4 transposed weights), one kernel.
// Sections: [0,8192) X | [8192,12288) Wq | [12288,12800) Wk |
//           [12800,13312) Wv | [13312,17408) Wo
// ---------------------------------------------------------------------------
__device__ __forceinline__ void conv_T_tile(
    const float* __restrict__ W, __half* __restrict__ WT,
    int N, int K, int bx, int by, float* tile /* [32][33] */)
{
    int n0 = bx * 32, k0 = by * 32;
    int tx = threadIdx.x & 31, ty = threadIdx.x >> 5;
#pragma unroll
    for (int j = 0; j < 4; ++j)
        tile[(ty + 8 * j) * 33 + tx] = W[(size_t)(k0 + ty + 8 * j) * N + n0 + tx];
    __syncthreads();
#pragma unroll
    for (int j = 0; j < 4; ++j) {
        int nn = n0 + ty + 8 * j;
        WT[(size_t)nn * K + k0 + tx] = __float2half_rn(tile[tx * 33 + ty + 8 * j]);
    }
}

__global__ __launch_bounds__(256)
void convert_all(const float* __restrict__ X,
                 const float* __restrict__ Wq, const float* __restrict__ Wk,
                 const float* __restrict__ Wv, const float* __restrict__ Wo,
                 __half* __restrict__ xh, __half* __restrict__ wqh,
                 __half* __restrict__ wkh, __half* __restrict__ wvh,
                 __half* __restrict__ woh)
{
    __shared__ float tile[32 * 33];
    int id = blockIdx.x;
    if (id < 8192) {
        size_t i = ((size_t)id * 256 + threadIdx.x) * 4;
        float4 v = *(const float4*)(X + i);
        *(__half2*)(xh + i)     = __floats2half2_rn(v.x, v.y);
        *(__half2*)(xh + i + 2) = __floats2half2_rn(v.z, v.w);
        return;
    }
    id -= 8192;
    if (id < 4096)      { conv_T_tile(Wq, wqh, HID, HID, id & 63, id >> 6, tile); return; }
    id -= 4096;
    if (id < 512)       { conv_T_tile(Wk, wkh, KVD, HID, id & 7,  id >> 3, tile); return; }
    id -= 512;
    if (id < 512)       { conv_T_tile(Wv, wvh, KVD, HID, id & 7,  id >> 3, tile); return; }
    id -= 512;
    conv_T_tile(Wo, woh, HID, HID, id & 63, id >> 6, tile);
}

// ---------------------------------------------------------------------------
// QKV GEMM: 64x128 tiles, 128 threads, 4 warps (2m x 2n), warp tile 32x64.
// 4-stage cp.async, 61440 B smem -> 3 CTAs/SM. Outputs fp16.
// ---------------------------------------------------------------------------
__device__ void gemm64_body(
    const __half* __restrict__ A, const __half* __restrict__ B,
    const float* __restrict__ bias, __half* __restrict__ Ch,
    int ldc, int m0, int n0, float scale, char* smb)
{
    const int t    = threadIdx.x;
    const int lane = t & 31, wid = t >> 5;
    const int wm   = wid & 1;        // 0..1 (32-row half)
    const int wn   = wid >> 1;       // 0..1 (64-col half)
    const int g    = lane >> 2;
    const int tg   = lane & 3;
    const int l15  = lane & 15, l7 = lane & 7;
    const int hi16 = lane >> 4;
    const int k8   = (lane >> 3) & 1;
    const uint32_t sb = smem_u32(smb);

    float acc[2][8][4];
#pragma unroll
    for (int im = 0; im < 2; ++im)
#pragma unroll
        for (int in = 0; in < 8; ++in)
#pragma unroll
            for (int r = 0; r < 4; ++r) acc[im][in][r] = 0.f;

    auto prefetch = [&](int s) {
        const uint32_t base = sb + (uint32_t)(s & 3) * STAGE64;
        const int k0 = s * 32;
        // A: 64 rows x 4 chunks = 256 chunks
#pragma unroll
        for (int i = 0; i < 2; ++i) {
            int idx = t + 128 * i;
            int r = idx >> 2, c = idx & 3;
            cp16(base + (uint32_t)(r * LDT + c * 8) * 2,
                 A + (size_t)(m0 + r) * HID + k0 + c * 8);
        }
        // B: 128 rows x 4 chunks = 512 chunks
#pragma unroll
        for (int i = 0; i < 4; ++i) {
            int idx = t + 128 * i;
            int r = idx >> 2, c = idx & 3;
            cp16(base + ATILE64 + (uint32_t)(r * LDT + c * 8) * 2,
                 B + (size_t)(n0 + r) * HID + k0 + c * 8);
        }
        CP_COMMIT();
    };

    prefetch(0); prefetch(1); prefetch(2);

    for (int s = 0; s < 64; ++s) {
        if (s < 62)       asm volatile("cp.async.wait_group 2;" ::: "memory");
        else if (s == 62) asm volatile("cp.async.wait_group 1;" ::: "memory");
        else              asm volatile("cp.async.wait_group 0;" ::: "memory");
        __syncthreads();
        if (s + 3 < 64) prefetch(s + 3);

        const uint32_t base = sb + (uint32_t)(s & 3) * STAGE64;
#pragma unroll
        for (int kk = 0; kk < 32; kk += 16) {
            uint32_t ah[2][4], bh[8][2];
#pragma unroll
            for (int im = 0; im < 2; ++im) {
                uint32_t ao = base +
                    (uint32_t)((wm * 32 + im * 16 + l15) * LDT + kk) * 2 + hi16 * 16;
                ldsm_x4(ah[im][0], ah[im][1], ah[im][2], ah[im][3], ao);
            }
#pragma unroll
            for (int p = 0; p < 4; ++p) {
                uint32_t bo = base + ATILE64 +
                    (uint32_t)((wn * 64 + p * 16 + l7 + hi16 * 8) * LDT + kk) * 2 + k8 * 16;
                uint32_t r0, r1, r2, r3;
                ldsm_x4(r0, r1, r2, r3, bo);
                bh[2 * p][0] = r0;     bh[2 * p][1] = r1;
                bh[2 * p + 1][0] = r2; bh[2 * p + 1][1] = r3;
            }
#pragma unroll
            for (int im = 0; im < 2; ++im)
#pragma unroll
                for (int in = 0; in < 8; ++in)
                    mma_fp16(acc[im][in], ah[im], bh[in]);
        }
    }

    // Epilogue: + bias, * scale, fp16 out
#pragma unroll
    for (int im = 0; im < 2; ++im) {
#pragma unroll
        for (int in = 0; in < 8; ++in) {
            int row = m0 + wm * 32 + im * 16 + g;
            int col = n0 + wn * 64 + in * 8 + 2 * tg;
            float2 b2 = *(const float2*)(bias + col);
            *(__half2*)(Ch + (size_t)row * ldc + col) =
                __floats2half2_rn((acc[im][in][0] + b2.x) * scale,
                                  (acc[im][in][1] + b2.y) * scale);
            *(__half2*)(Ch + (size_t)(row + 8) * ldc + col) =
                __floats2half2_rn((acc[im][in][2] + b2.x) * scale,
                                  (acc[im][in][3] + b2.y) * scale);
        }
    }
}

// QKV: grid = 1280 (gx = bid>>6 in [0,20), my = bid&63), block 128, 3 CTAs/SM.
__global__ __launch_bounds__(128, 3)
void qkv_mma(const float* __restrict__ bq, const float* __restrict__ bk,
             const float* __restrict__ bv)
{
    extern __shared__ char smb[];
    int gx = blockIdx.x >> 6, my = blockIdx.x & 63;
    int m0 = my * 64;
    if (gx < 16) {
        gemm64_body(g_Xh, g_WqTh, bq, g_Qh, HID, m0, gx * 128, SCALING, smb);
    } else if (gx < 18) {
        gemm64_body(g_Xh, g_WkTh, bk, g_Kh, KVD, m0, (gx - 16) * 128, 1.f, smb);
    } else {
        gemm64_body(g_Xh, g_WvTh, bv, g_Vh, KVD, m0, (gx - 18) * 128, 1.f, smb);
    }
}

// ---------------------------------------------------------------------------
// O-proj GEMM (v2, proven): 128x128 tile, 128 threads, warp tile 64x64.
// ---------------------------------------------------------------------------
__global__ __launch_bounds__(128, 2)
void oproj_mma(const float* __restrict__ bo, float* __restrict__ out)
{
    extern __shared__ char smb[];
    const int t    = threadIdx.x;
    const int lane = t & 31, wid = t >> 5;
    const int wm   = wid & 1, wn = wid >> 1;
    const int g    = lane >> 2, tg = lane & 3;
    const int l15  = lane & 15, l7 = lane & 7;
    const int hi16 = lane >> 4, k8 = (lane >> 3) & 1;
    const int m0 = blockIdx.y * 128, n0 = blockIdx.x * 128;
    const uint32_t sb = smem_u32(smb);
    const __half* A = g_ATh;
    const __half* B = g_WoTh;

    float acc[4][8][4];
#pragma unroll
    for (int im = 0; im < 4; ++im)
#pragma unroll
        for (int in = 0; in < 8; ++in)
#pragma unroll
            for (int r = 0; r < 4; ++r) acc[im][in][r] = 0.f;

    auto prefetch = [&](int s) {
        const uint32_t base = sb + (uint32_t)(s & 3) * STAGE;
        const int k0 = s * 32;
#pragma unroll
        for (int i = 0; i < 4; ++i) {
            int idx = t + 128 * i;
            int r = idx >> 2, c = idx & 3;
            uint32_t so = base + (uint32_t)(r * LDT + c * 8) * 2;
            cp16(so,         A + (size_t)(m0 + r) * HID + k0 + c * 8);
            cp16(so + TILEB, B + (size_t)(n0 + r) * HID + k0 + c * 8);
        }
        CP_COMMIT();
    };

    prefetch(0); prefetch(1); prefetch(2);

    for (int s = 0; s < 64; ++s) {
        if (s < 62)       asm volatile("cp.async.wait_group 2;" ::: "memory");
        else if (s == 62) asm volatile("cp.async.wait_group 1;" ::: "memory");
        else              asm volatile("cp.async.wait_group 0;" ::: "memory");
        __syncthreads();
        if (s + 3 < 64) prefetch(s + 3);

        const uint32_t base = sb + (uint32_t)(s & 3) * STAGE;
#pragma unroll
        for (int kk = 0; kk < 32; kk += 16) {
            uint32_t ah[4][4], bh[8][2];
#pragma unroll
            for (int im = 0; im < 4; ++im) {
                uint32_t ao = base +
                    (uint32_t)((wm * 64 + im * 16 + l15) * LDT + kk) * 2 + hi16 * 16;
                ldsm_x4(ah[im][0], ah[im][1], ah[im][2], ah[im][3], ao);
            }
#pragma unroll
            for (int p = 0; p < 4; ++p) {
                uint32_t bo = base + TILEB +
                    (uint32_t)((wn * 64 + p * 16 + l7 + hi16 * 8) * LDT + kk) * 2 + k8 * 16;
                uint32_t r0, r1, r2, r3;
                ldsm_x4(r0, r1, r2, r3, bo);
                bh[2 * p][0] = r0;     bh[2 * p][1] = r1;
                bh[2 * p + 1][0] = r2; bh[2 * p + 1][1] = r3;
            }
#pragma unroll
            for (int im = 0; im < 4; ++im)
#pragma unroll
                for (int in = 0; in < 8; ++in)
                    mma_fp16(acc[im][in], ah[im], bh[in]);
        }
    }

#pragma unroll
    for (int im = 0; im < 4; ++im) {
#pragma unroll
        for (int in = 0; in < 8; ++in) {
            int row = m0 + wm * 64 + im * 16 + g;
            int col = n0 + wn * 64 + in * 8 + 2 * tg;
            float2 b2 = *(const float2*)(bo + col);
            *(float2*)(out + (size_t)row * HID + col) =
                make_float2(acc[im][in][0] + b2.x, acc[im][in][1] + b2.y);
            *(float2*)(out + (size_t)(row + 8) * HID + col) =
                make_float2(acc[im][in][2] + b2.x, acc[im][in][3] + b2.y);
        }
    }
}

// ---------------------------------------------------------------------------
// Flash attention (unchanged — proven).
// grid = (32 qblocks, 32 bh), 128 threads, Br=64, Bc=64, D=128.
// ---------------------------------------------------------------------------
#define FL_LDK  136
#define FL_TILE (64 * FL_LDK * 2)        // 17408 B
#define FL_SMEM (5 * FL_TILE)            // 87040 B

__global__ __launch_bounds__(128, 2)
void flash_mma()
{
    extern __shared__ __half fsm[];
    const uint32_t sQ  = smem_u32(fsm);
    const uint32_t sK0 = sQ + FL_TILE;
    const uint32_t sV0 = sQ + 3 * FL_TILE;

    const int t = threadIdx.x, lane = t & 31, warp = t >> 5;
    const int g = lane >> 2, tg = lane & 3;
    const int l15 = lane & 15, l7 = lane & 7;
    const int hi16 = lane >> 4, k8 = (lane >> 3) & 1;
    const int bh = blockIdx.y, b = bh >> 4, h = bh & 15, kvh = h >> 3;
    const int q0 = blockIdx.x * 64;
    const size_t qrow0 = (size_t)(b * 2048 + q0);
    const int wr = warp * 16;

    auto prefetch_kv = [&](int kb) {
        const uint32_t buf = (uint32_t)(kb & 1) * FL_TILE;
        const size_t krow0 = (size_t)(b * 2048 + kb * 64);
#pragma unroll
        for (int s = 0; s < 8; ++s) {
            int i = t + 128 * s;
            int r = i >> 4, c = i & 15;
            uint32_t so = (uint32_t)(r * FL_LDK + c * 8) * 2;
            size_t go = (krow0 + r) * KVD + kvh * HD + c * 8;
            cp16(sK0 + buf + so, g_Kh + go);
            cp16(sV0 + buf + so, g_Vh + go);
        }
        CP_COMMIT();
    };

    prefetch_kv(0);

#pragma unroll
    for (int s = 0; s < 8; ++s) {
        int i = t + 128 * s;
        int r = i >> 4, c = i & 15;
        *(uint4*)(fsm + r * FL_LDK + c * 8) =
            *(const uint4*)(g_Qh + (qrow0 + r) * HID + h * HD + c * 8);
    }
    __syncthreads();

    uint32_t aQ[8][4];
#pragma unroll
    for (int ks = 0; ks < 8; ++ks) {
        uint32_t ao = sQ + (uint32_t)((wr + l15) * FL_LDK + ks * 16) * 2 + hi16 * 16;
        ldsm_x4(aQ[ks][0], aQ[ks][1], aQ[ks][2], aQ[ks][3], ao);
    }

    float oacc[16][4];
#pragma unroll
    for (int j = 0; j < 16; ++j)
#pragma unroll
        for (int r = 0; r < 4; ++r) oacc[j][r] = 0.f;
    float mrow0 = -1e30f, mrow1 = -1e30f, lrow0 = 0.f, lrow1 = 0.f;

    for (int kb = 0; kb < 32; ++kb) {
        asm volatile("cp.async.wait_group 0;" ::: "memory");
        __syncthreads();
        if (kb + 1 < 32) prefetch_kv(kb + 1);

        const uint32_t sK = sK0 + (uint32_t)(kb & 1) * FL_TILE;
        const uint32_t sV = sV0 + (uint32_t)(kb & 1) * FL_TILE;

        float sacc[8][4];
#pragma unroll
        for (int j = 0; j < 8; ++j)
#pragma unroll
            for (int r = 0; r < 4; ++r) sacc[j][r] = 0.f;
#pragma unroll
        for (int ks = 0; ks < 8; ++ks) {
#pragma unroll
            for (int p = 0; p < 4; ++p) {
                uint32_t bo = sK +
                    (uint32_t)((p * 16 + l7 + hi16 * 8) * FL_LDK + ks * 16) * 2 + k8 * 16;
                uint32_t r0, r1, r2, r3;
                ldsm_x4(r0, r1, r2, r3, bo);
                uint32_t b0[2] = {r0, r1}, b1[2] = {r2, r3};
                mma_fp16(sacc[2 * p], aQ[ks], b0);
                mma_fp16(sacc[2 * p + 1], aQ[ks], b1);
            }
        }

        float mx0 = -1e30f, mx1 = -1e30f;
#pragma unroll
        for (int j = 0; j < 8; ++j) {
            mx0 = fmaxf(mx0, fmaxf(sacc[j][0], sacc[j][1]));
            mx1 = fmaxf(mx1, fmaxf(sacc[j][2], sacc[j][3]));
        }
        mx0 = fmaxf(mx0, __shfl_xor_sync(0xffffffffu, mx0, 1));
        mx0 = fmaxf(mx0, __shfl_xor_sync(0xffffffffu, mx0, 2));
        mx1 = fmaxf(mx1, __shfl_xor_sync(0xffffffffu, mx1, 1));
        mx1 = fmaxf(mx1, __shfl_xor_sync(0xffffffffu, mx1, 2));
        float mn0 = fmaxf(mrow0, mx0), mn1 = fmaxf(mrow1, mx1);
        float al0 = __expf(mrow0 - mn0), al1 = __expf(mrow1 - mn1);
        mrow0 = mn0; mrow1 = mn1;

        uint32_t aP[4][4];
        float s0 = 0.f, s1 = 0.f;
#pragma unroll
        for (int j = 0; j < 8; ++j) {
            float p0 = __expf(sacc[j][0] - mn0);
            float p1 = __expf(sacc[j][1] - mn0);
            float p2 = __expf(sacc[j][2] - mn1);
            float p3 = __expf(sacc[j][3] - mn1);
            s0 += p0 + p1; s1 += p2 + p3;
            __half2 h01 = __floats2half2_rn(p0, p1);
            __half2 h23 = __floats2half2_rn(p2, p3);
            int ks = j >> 1, hi = (j & 1) * 2;
            aP[ks][hi]     = *(uint32_t*)&h01;
            aP[ks][hi + 1] = *(uint32_t*)&h23;
        }
        s0 += __shfl_xor_sync(0xffffffffu, s0, 1);
        s0 += __shfl_xor_sync(0xffffffffu, s0, 2);
        s1 += __shfl_xor_sync(0xffffffffu, s1, 1);
        s1 += __shfl_xor_sync(0xffffffffu, s1, 2);
        lrow0 = lrow0 * al0 + s0;
        lrow1 = lrow1 * al1 + s1;

#pragma unroll
        for (int j = 0; j < 16; ++j) {
            oacc[j][0] *= al0; oacc[j][1] *= al0;
            oacc[j][2] *= al1; oacc[j][3] *= al1;
        }

#pragma unroll
        for (int ks = 0; ks < 4; ++ks) {
#pragma unroll
            for (int p = 0; p < 8; ++p) {
                uint32_t vo = sV +
                    (uint32_t)((ks * 16 + l7 + k8 * 8) * FL_LDK) * 2 + (2 * p + hi16) * 16;
                uint32_t r0, r1, r2, r3;
                ldsm_x4_t(r0, r1, r2, r3, vo);
                uint32_t b0[2] = {r0, r1}, b1[2] = {r2, r3};
                mma_fp16(oacc[2 * p], aP[ks], b0);
                mma_fp16(oacc[2 * p + 1], aP[ks], b1);
            }
        }
    }

    float i0 = 1.f / lrow0, i1 = 1.f / lrow1;
    size_t row0 = qrow0 + wr + g;
#pragma unroll
    for (int j = 0; j < 16; ++j) {
        int col = h * HD + 8 * j + 2 * tg;
        *(__half2*)(g_ATh + row0 * HID + col) =
            __floats2half2_rn(oacc[j][0] * i0, oacc[j][1] * i0);
        *(__half2*)(g_ATh + (row0 + 8) * HID + col) =
            __floats2half2_rn(oacc[j][2] * i1, oacc[j][3] * i1);
    }
}

// ---------------------------------------------------------------------------
extern "C" void kernel_launch(void* const* d_in, const int* in_sizes, int n_in,
                              void* d_out, int out_size)
{
    (void)in_sizes; (void)n_in; (void)out_size;
    const float* X  = (const float*)d_in[0];
    const float* Wq = (const float*)d_in[1];
    const float* bq = (const float*)d_in[2];
    const float* Wk = (const float*)d_in[3];
    const float* bk = (const float*)d_in[4];
    const float* Wv = (const float*)d_in[5];
    const float* bv = (const float*)d_in[6];
    const float* Wo = (const float*)d_in[7];
    const float* bo = (const float*)d_in[8];
    float* out = (float*)d_out;

    (void)cudaFuncSetAttribute(flash_mma,
        cudaFuncAttributeMaxDynamicSharedMemorySize, FL_SMEM);
    (void)cudaFuncSetAttribute(qkv_mma,
        cudaFuncAttributeMaxDynamicSharedMemorySize, GSMEM64);
    (void)cudaFuncSetAttribute(oproj_mma,
        cudaFuncAttributeMaxDynamicSharedMemorySize, GSMEM);

    __half *xh, *wqh, *wkh, *wvh, *woh;
    cudaGetSymbolAddress((void**)&xh,  g_Xh);
    cudaGetSymbolAddress((void**)&wqh, g_WqTh);
    cudaGetSymbolAddress((void**)&wkh, g_WkTh);
    cudaGetSymbolAddress((void**)&wvh, g_WvTh);
    cudaGetSymbolAddress((void**)&woh, g_WoTh);

    // 1) merged converts to fp16 (X + 4 weight transposes)
    convert_all<<<17408, 256>>>(X, Wq, Wk, Wv, Wo, xh, wqh, wkh, wvh, woh);

    // 2) QKV projection (64x128 tiles, 3 CTAs/SM)
    qkv_mma<<<1280, 128, GSMEM64>>>(bq, bk, bv);

    // 3) attention (fp16 mma.sync flash)
    flash_mma<<<dim3(32, 32), 128, FL_SMEM>>>();

    // 4) O projection (128x128 tiles)
    oproj_mma<<<dim3(16, 32), 128, GSMEM>>>(bo, out);
}